// round 7
// baseline (speedup 1.0000x reference)
#include <cuda_runtime.h>
#include <cuda_fp16.h>
#include <cstdint>

// ============================================================================
// Problem sizes (fixed for this dataset)
// ============================================================================
static constexpr int DIMN  = 4096;
static constexpr int HID   = 11008;
static constexpr int MROWS = 8192;   // B*S = 4*2048

// ============================================================================
// Device scratch (allocation-free rule: __device__ globals)
// ============================================================================
static __device__ __align__(256) __half g_x  [(size_t)MROWS * DIMN];
static __device__ __align__(256) __half g_wg [(size_t)HID   * DIMN];
static __device__ __align__(256) __half g_wu [(size_t)HID   * DIMN];
static __device__ __align__(256) __half g_wd [(size_t)DIMN  * HID ];
static __device__ __align__(256) __half g_mid[(size_t)MROWS * HID ];

// ============================================================================
// PTX helpers — compute_103-safe only (cp.async, ldmatrix, mma.sync.m16n8k16)
// ============================================================================
__device__ __forceinline__ uint32_t smem_to_u32(const void* smem_ptr) {
    uint32_t addr;
    asm("{ .reg .u64 tmp; cvta.to.shared.u64 tmp, %1; cvt.u32.u64 %0, tmp; }"
        : "=r"(addr) : "l"(smem_ptr));
    return addr;
}

__device__ __forceinline__ void cp_async16(uint32_t dst, const void* src) {
    asm volatile("cp.async.cg.shared.global [%0], [%1], 16;\n"
                 :: "r"(dst), "l"(src) : "memory");
}
#define CP_COMMIT() asm volatile("cp.async.commit_group;\n" ::: "memory")
template <int N>
__device__ __forceinline__ void cp_wait() {
    asm volatile("cp.async.wait_group %0;\n" :: "n"(N) : "memory");
}

__device__ __forceinline__ void ldsm_x4(uint32_t& r0, uint32_t& r1,
                                        uint32_t& r2, uint32_t& r3, uint32_t addr) {
    asm volatile("ldmatrix.sync.aligned.m8n8.x4.shared.b16 {%0,%1,%2,%3}, [%4];"
                 : "=r"(r0), "=r"(r1), "=r"(r2), "=r"(r3) : "r"(addr));
}

__device__ __forceinline__ void mma16816(float* c, const uint32_t* a, const uint32_t* b) {
    asm volatile(
        "mma.sync.aligned.m16n8k16.row.col.f32.f16.f16.f32 "
        "{%0,%1,%2,%3}, {%4,%5,%6,%7}, {%8,%9}, {%0,%1,%2,%3};"
        : "+f"(c[0]), "+f"(c[1]), "+f"(c[2]), "+f"(c[3])
        : "r"(a[0]), "r"(a[1]), "r"(a[2]), "r"(a[3]), "r"(b[0]), "r"(b[1]));
}

// fp16-accumulate variant: c = {c0c1, c2c3} packed half2, 2 regs
__device__ __forceinline__ void mma16816h(uint32_t* c, const uint32_t* a,
                                          const uint32_t* b) {
    asm volatile(
        "mma.sync.aligned.m16n8k16.row.col.f16.f16.f16.f16 "
        "{%0,%1}, {%2,%3,%4,%5}, {%6,%7}, {%0,%1};"
        : "+r"(c[0]), "+r"(c[1])
        : "r"(a[0]), "r"(a[1]), "r"(a[2]), "r"(a[3]), "r"(b[0]), "r"(b[1]));
}

// ============================================================================
// Merged dequant/convert: one launch covering x (f32->f16) and the three
// weights (i32->f16). Block ranges select the tensor.
// ============================================================================
static constexpr int N8X = (MROWS * DIMN) / 8;   // 4,194,304 -> 16384 blocks
static constexpr int N8W = (HID * DIMN) / 8;     // 5,636,096 -> 22016 blocks
static constexpr int BX  = N8X / 256;            // 16384
static constexpr int BW  = N8W / 256;            // 22016

__global__ void __launch_bounds__(256) cvt_all(
    const float4* __restrict__ x, const int4* __restrict__ wg,
    const int4* __restrict__ wu, const int4* __restrict__ wd,
    uint4* __restrict__ ox, uint4* __restrict__ owg,
    uint4* __restrict__ owu, uint4* __restrict__ owd)
{
    int b = blockIdx.x;
    if (b < BX) {
        int i = b * 256 + threadIdx.x;
        float4 a = x[2 * i];
        float4 c = x[2 * i + 1];
        __half2 h0 = __floats2half2_rn(a.x, a.y);
        __half2 h1 = __floats2half2_rn(a.z, a.w);
        __half2 h2 = __floats2half2_rn(c.x, c.y);
        __half2 h3 = __floats2half2_rn(c.z, c.w);
        uint4 r;
        r.x = *reinterpret_cast<uint32_t*>(&h0);
        r.y = *reinterpret_cast<uint32_t*>(&h1);
        r.z = *reinterpret_cast<uint32_t*>(&h2);
        r.w = *reinterpret_cast<uint32_t*>(&h3);
        ox[i] = r;
        return;
    }
    b -= BX;
    const int4* src;
    uint4* dst;
    if (b < BW)            { src = wg; dst = owg; }
    else if (b < 2 * BW)   { src = wu; dst = owu; b -= BW; }
    else                   { src = wd; dst = owd; b -= 2 * BW; }
    int i = b * 256 + threadIdx.x;
    int4 a = src[2 * i];
    int4 c = src[2 * i + 1];
    __half2 h0 = __halves2half2(__int2half_rn(a.x), __int2half_rn(a.y));
    __half2 h1 = __halves2half2(__int2half_rn(a.z), __int2half_rn(a.w));
    __half2 h2 = __halves2half2(__int2half_rn(c.x), __int2half_rn(c.y));
    __half2 h3 = __halves2half2(__int2half_rn(c.z), __int2half_rn(c.w));
    uint4 r;
    r.x = *reinterpret_cast<uint32_t*>(&h0);
    r.y = *reinterpret_cast<uint32_t*>(&h1);
    r.z = *reinterpret_cast<uint32_t*>(&h2);
    r.w = *reinterpret_cast<uint32_t*>(&h3);
    dst[i] = r;
}

// ============================================================================
// Multistage cp.async + mma.sync GEMM (C = A * B^T), fp16 in.
//   NB==2 (BN_EACH=128): gate+up; fp16 accumulation WITHIN each 64-k chunk
//       (two-level: promote to fp32 master acc once per chunk; g-outer loop
//       keeps fp16 live state to 16 regs). Fused SwiGLU -> fp16 mid.
//       Chunk partial sums bounded (|seg| < ~4e3 << 65504): no overflow.
//   NB==1 (BN_EACH=256): down proj; fp32 accumulation (products too large
//       for safe fp16 segment sums). Scaled fp32 out.
// CTA tile: 128(m) x 256(n-total) x 64(k). 512 threads = 16 warps as 4m x 4n.
// SMEM rows 64 halves = 128B, XOR-swizzled: byte[6:4] ^= row[2:0].
// ============================================================================
template <int NB, int BN_EACH, int STAGES>
__global__ void __launch_bounds__(512, 1) ffn_gemm(
    const __half* __restrict__ A,
    const __half* __restrict__ B0,
    const __half* __restrict__ B1,
    void* __restrict__ outp,
    const float* __restrict__ s0p,
    const float* __restrict__ s1p,
    int K, int ntiles, int ncols)
{
    constexpr int BM = 128, BK = 64;
    constexpr int NTHR = 512;
    constexpr int WN_COLS = BN_EACH / 4;          // warp n-slice per matrix: 32/64
    constexpr int MI   = 2;                        // m16 groups per warp (32 rows)
    constexpr int NMMA = WN_COLS / 8;              // n8 mmas per warp per matrix: 4/8
    constexpr int NJ   = NB * (NMMA / 2);
    constexpr int A_BYTES = BM * BK * 2;           // 16384
    constexpr int B_BYTES = BN_EACH * BK * 2;
    constexpr int STAGE_BYTES = A_BYTES + NB * B_BYTES;   // 49152
    constexpr int A_ITERS = (BM * 8) / NTHR;       // 2
    constexpr int B_ITERS = (BN_EACH * 8) / NTHR;  // 2 or 4

    extern __shared__ char smem[];
    const uint32_t sb = smem_to_u32(smem);

    const int tid  = threadIdx.x;
    const int wid  = tid >> 5;
    const int lane = tid & 31;
    const int wm   = wid & 3;       // 0..3 (m)
    const int wn   = wid >> 2;      // 0..3 (n)
    const int quad = lane >> 3;     // 0..3
    const int qr   = lane & 7;

    // L2-friendly tile mapping
    constexpr int GM = 8;
    const int tpg = GM * ntiles;
    const int grp = blockIdx.x / tpg;
    const int rem = blockIdx.x % tpg;
    const int mt  = grp * GM + (rem % GM);
    const int nt  = rem / GM;

    const int kch = K / BK;

    float acc[NB][MI][NMMA][4];
#pragma unroll
    for (int g = 0; g < NB; g++)
#pragma unroll
        for (int mi = 0; mi < MI; mi++)
#pragma unroll
            for (int ni = 0; ni < NMMA; ni++)
#pragma unroll
                for (int q = 0; q < 4; q++) acc[g][mi][ni][q] = 0.f;

    // ---- affine loader bases ----
    const int lrow = tid >> 3;                    // 0..63
    const int lch  = tid & 7;
    const uint32_t ldst = lrow * 128 + ((lch * 16) ^ ((lrow & 7) << 4));
    const __half* aP = A + (size_t)(mt * BM + lrow) * K + lch * 8;
    const __half* bP[2];
    bP[0] = B0 + (size_t)(nt * BN_EACH + lrow) * K + lch * 8;
    bP[1] = B1 + (size_t)(nt * BN_EACH + lrow) * K + lch * 8;
    const size_t rstep = (size_t)64 * K;

    auto load_stage = [&](int kc, int slot) {
        const uint32_t st = sb + slot * STAGE_BYTES + ldst;
        const int k0 = kc * BK;
#pragma unroll
        for (int it = 0; it < A_ITERS; it++)
            cp_async16(st + it * 8192, aP + k0 + it * rstep);
#pragma unroll
        for (int g = 0; g < NB; g++) {
            const __half* bp = bP[g] + k0;
            const uint32_t bbase = st + A_BYTES + g * B_BYTES;
#pragma unroll
            for (int it = 0; it < B_ITERS; it++)
                cp_async16(bbase + it * 8192, bp + it * rstep);
        }
    };

    // ---- prologue ----
#pragma unroll
    for (int s = 0; s < STAGES - 1; s++) {
        load_stage(s, s);
        CP_COMMIT();
    }

    // ---- main loop ----
    for (int kc = 0; kc < kch; kc++) {
        __syncthreads();
        const int pre = kc + STAGES - 1;
        if (pre < kch) load_stage(pre, pre % STAGES);
        CP_COMMIT();
        cp_wait<STAGES - 1>();
        __syncthreads();

        const uint32_t st = sb + (kc % STAGES) * STAGE_BYTES;

        if constexpr (NB == 2) {
            // ---- fp16 chunk accumulation, g-outer (gate then up) ----
#pragma unroll
            for (int g = 0; g < 2; g++) {
                uint32_t hacc[MI][NMMA][2];
#pragma unroll
                for (int mi = 0; mi < MI; mi++)
#pragma unroll
                    for (int ni = 0; ni < NMMA; ni++) {
                        hacc[mi][ni][0] = 0u;
                        hacc[mi][ni][1] = 0u;
                    }
#pragma unroll
                for (int ks = 0; ks < 4; ks++) {
                    uint32_t fa[MI][4];
#pragma unroll
                    for (int mi = 0; mi < MI; mi++) {
                        int row  = wm * 32 + mi * 16 + (quad & 1) * 8 + qr;
                        int colb = ks * 32 + (quad >> 1) * 16;
                        uint32_t ad = st + row * 128 + (colb ^ ((row & 7) << 4));
                        ldsm_x4(fa[mi][0], fa[mi][1], fa[mi][2], fa[mi][3], ad);
                    }
                    uint32_t fb[NMMA / 2][4];
#pragma unroll
                    for (int j = 0; j < NMMA / 2; j++) {
                        int row  = wn * WN_COLS + j * 16 + (quad >> 1) * 8 + qr;
                        int colb = ks * 32 + (quad & 1) * 16;
                        uint32_t bd = st + A_BYTES + g * B_BYTES + row * 128 +
                                      (colb ^ ((row & 7) << 4));
                        ldsm_x4(fb[j][0], fb[j][1], fb[j][2], fb[j][3], bd);
                    }
#pragma unroll
                    for (int mi = 0; mi < MI; mi++)
#pragma unroll
                        for (int ni = 0; ni < NMMA; ni++)
                            mma16816h(hacc[mi][ni], fa[mi],
                                      &fb[ni >> 1][(ni & 1) * 2]);
                }
                // promote chunk partials to fp32 master
#pragma unroll
                for (int mi = 0; mi < MI; mi++)
#pragma unroll
                    for (int ni = 0; ni < NMMA; ni++) {
                        float2 f0 = __half22float2(
                            *reinterpret_cast<__half2*>(&hacc[mi][ni][0]));
                        float2 f1 = __half22float2(
                            *reinterpret_cast<__half2*>(&hacc[mi][ni][1]));
                        acc[g][mi][ni][0] += f0.x;
                        acc[g][mi][ni][1] += f0.y;
                        acc[g][mi][ni][2] += f1.x;
                        acc[g][mi][ni][3] += f1.y;
                    }
            }
        } else {
            // ---- fp32 accumulation (down proj) ----
#pragma unroll
            for (int ks = 0; ks < 4; ks++) {
                uint32_t fa[MI][4];
#pragma unroll
                for (int mi = 0; mi < MI; mi++) {
                    int row  = wm * 32 + mi * 16 + (quad & 1) * 8 + qr;
                    int colb = ks * 32 + (quad >> 1) * 16;
                    uint32_t ad = st + row * 128 + (colb ^ ((row & 7) << 4));
                    ldsm_x4(fa[mi][0], fa[mi][1], fa[mi][2], fa[mi][3], ad);
                }
                uint32_t fb[NJ][4];
#pragma unroll
                for (int j = 0; j < NMMA / 2; j++) {
                    int row  = wn * WN_COLS + j * 16 + (quad >> 1) * 8 + qr;
                    int colb = ks * 32 + (quad & 1) * 16;
                    uint32_t bd = st + A_BYTES + row * 128 +
                                  (colb ^ ((row & 7) << 4));
                    ldsm_x4(fb[j][0], fb[j][1], fb[j][2], fb[j][3], bd);
                }
#pragma unroll
                for (int mi = 0; mi < MI; mi++)
#pragma unroll
                    for (int ni = 0; ni < NMMA; ni++)
                        mma16816(acc[0][mi][ni], fa[mi],
                                 &fb[ni >> 1][(ni & 1) * 2]);
            }
        }
    }

    // ---- epilogue ----
    const float s0 = *s0p;
    const float s1 = *s1p;
    if (NB == 2) {
        __half* out = (__half*)outp;
#pragma unroll
        for (int mi = 0; mi < MI; mi++)
#pragma unroll
            for (int ni = 0; ni < NMMA; ni++) {
                int row0 = mt * BM + wm * 32 + mi * 16 + (lane >> 2);
                int col  = nt * BN_EACH + wn * WN_COLS + ni * 8 + (lane & 3) * 2;
#pragma unroll
                for (int h = 0; h < 2; h++) {
                    int row = row0 + h * 8;
                    float g0 = s0 * acc[0][mi][ni][2 * h + 0];
                    float g1 = s0 * acc[0][mi][ni][2 * h + 1];
                    float u0 = s1 * acc[1][mi][ni][2 * h + 0];
                    float u1 = s1 * acc[1][mi][ni][2 * h + 1];
                    float r0 = g0 / (1.f + __expf(-g0)) * u0;
                    float r1 = g1 / (1.f + __expf(-g1)) * u1;
                    *(__half2*)(out + (size_t)row * ncols + col) =
                        __floats2half2_rn(r0, r1);
                }
            }
    } else {
        float* out = (float*)outp;
#pragma unroll
        for (int mi = 0; mi < MI; mi++)
#pragma unroll
            for (int ni = 0; ni < NMMA; ni++) {
                int row0 = mt * BM + wm * 32 + mi * 16 + (lane >> 2);
                int col  = nt * BN_EACH + wn * WN_COLS + ni * 8 + (lane & 3) * 2;
#pragma unroll
                for (int h = 0; h < 2; h++) {
                    int row = row0 + h * 8;
                    float2 v;
                    v.x = s0 * acc[0][mi][ni][2 * h + 0];
                    v.y = s0 * acc[0][mi][ni][2 * h + 1];
                    *(float2*)(out + (size_t)row * ncols + col) = v;
                }
            }
    }
}

// ============================================================================
// Host side
// ============================================================================
extern "C" void kernel_launch(void* const* d_in, const int* in_sizes, int n_in,
                              void* d_out, int out_size) {
    const float* x  = (const float*)d_in[0];
    const int*   wg = (const int*)d_in[1];
    const int*   wu = (const int*)d_in[2];
    const int*   wd = (const int*)d_in[3];
    const float* sg = (const float*)d_in[4];
    const float* su = (const float*)d_in[5];
    const float* sd = (const float*)d_in[6];

    void *px, *pwg, *pwu, *pwd, *pmid;
    cudaGetSymbolAddress(&px,  g_x);
    cudaGetSymbolAddress(&pwg, g_wg);
    cudaGetSymbolAddress(&pwu, g_wu);
    cudaGetSymbolAddress(&pwd, g_wd);
    cudaGetSymbolAddress(&pmid, g_mid);

    // --- merged dequant / convert (one launch) ---
    cvt_all<<<BX + 3 * BW, 256>>>(
        (const float4*)x, (const int4*)wg, (const int4*)wu, (const int4*)wd,
        (uint4*)px, (uint4*)pwg, (uint4*)pwu, (uint4*)pwd);

    constexpr int STAGES = 4;
    constexpr int SMEM_BYTES = STAGES * 49152;   // 196608
    cudaFuncSetAttribute(ffn_gemm<2, 128, STAGES>,
                         cudaFuncAttributeMaxDynamicSharedMemorySize, SMEM_BYTES);
    cudaFuncSetAttribute(ffn_gemm<1, 256, STAGES>,
                         cudaFuncAttributeMaxDynamicSharedMemorySize, SMEM_BYTES);

    // GEMM1: fused gate+up+SwiGLU -> g_mid (fp16). fp16 chunk accumulation.
    {
        int mtiles = MROWS / 128;   // 64
        int ntiles = HID / 128;     // 86
        ffn_gemm<2, 128, STAGES><<<mtiles * ntiles, 512, SMEM_BYTES>>>(
            (const __half*)px, (const __half*)pwg, (const __half*)pwu,
            pmid, sg, su, DIMN, ntiles, HID);
    }
    // GEMM2: down projection -> d_out (fp32). fp32 accumulation.
    {
        int mtiles = MROWS / 128;   // 64
        int ntiles = DIMN / 256;    // 16
        ffn_gemm<1, 256, STAGES><<<mtiles * ntiles, 512, SMEM_BYTES>>>(
            (const __half*)pmid, (const __half*)pwd, (const __half*)pwd,
            d_out, sd, sd, HID, ntiles, DIMN);
    }
}

// round 8
// speedup vs baseline: 1.1007x; 1.1007x over previous
#include <cuda_runtime.h>
#include <cuda_fp16.h>
#include <cstdint>

// ============================================================================
// Problem sizes (fixed for this dataset)
// ============================================================================
static constexpr int DIMN  = 4096;
static constexpr int HID   = 11008;
static constexpr int MROWS = 8192;   // B*S = 4*2048

// ============================================================================
// Device scratch (allocation-free rule: __device__ globals)
// ============================================================================
static __device__ __align__(256) __half g_x  [(size_t)MROWS * DIMN];
static __device__ __align__(256) __half g_wg [(size_t)HID   * DIMN];
static __device__ __align__(256) __half g_wu [(size_t)HID   * DIMN];
static __device__ __align__(256) __half g_wd [(size_t)DIMN  * HID ];
static __device__ __align__(256) __half g_mid[(size_t)MROWS * HID ];

// ============================================================================
// PTX helpers — compute_103-safe only (cp.async, ldmatrix, mma.sync.m16n8k16)
// ============================================================================
__device__ __forceinline__ uint32_t smem_to_u32(const void* smem_ptr) {
    uint32_t addr;
    asm("{ .reg .u64 tmp; cvta.to.shared.u64 tmp, %1; cvt.u32.u64 %0, tmp; }"
        : "=r"(addr) : "l"(smem_ptr));
    return addr;
}

__device__ __forceinline__ void cp_async16(uint32_t dst, const void* src) {
    asm volatile("cp.async.cg.shared.global [%0], [%1], 16;\n"
                 :: "r"(dst), "l"(src) : "memory");
}
#define CP_COMMIT() asm volatile("cp.async.commit_group;\n" ::: "memory")
template <int N>
__device__ __forceinline__ void cp_wait() {
    asm volatile("cp.async.wait_group %0;\n" :: "n"(N) : "memory");
}

__device__ __forceinline__ void ldsm_x4(uint32_t& r0, uint32_t& r1,
                                        uint32_t& r2, uint32_t& r3, uint32_t addr) {
    asm volatile("ldmatrix.sync.aligned.m8n8.x4.shared.b16 {%0,%1,%2,%3}, [%4];"
                 : "=r"(r0), "=r"(r1), "=r"(r2), "=r"(r3) : "r"(addr));
}

__device__ __forceinline__ void mma16816(float* c, const uint32_t* a, const uint32_t* b) {
    asm volatile(
        "mma.sync.aligned.m16n8k16.row.col.f32.f16.f16.f32 "
        "{%0,%1,%2,%3}, {%4,%5,%6,%7}, {%8,%9}, {%0,%1,%2,%3};"
        : "+f"(c[0]), "+f"(c[1]), "+f"(c[2]), "+f"(c[3])
        : "r"(a[0]), "r"(a[1]), "r"(a[2]), "r"(a[3]), "r"(b[0]), "r"(b[1]));
}

// ============================================================================
// Converts, split into two launches so the ncu capture slot (-s 5 -c 1)
// lands on a GEMM: order is cvt_xw -> gemm1 -> cvt_wd -> gemm2.
// ============================================================================
static constexpr int N8X = (MROWS * DIMN) / 8;   // 4,194,304 -> 16384 blocks
static constexpr int N8W = (HID * DIMN) / 8;     // 5,636,096 -> 22016 blocks
static constexpr int BX  = N8X / 256;            // 16384
static constexpr int BW  = N8W / 256;            // 22016

__device__ __forceinline__ uint4 cvt_i32x8(const int4* src, int i) {
    int4 a = src[2 * i];
    int4 c = src[2 * i + 1];
    __half2 h0 = __halves2half2(__int2half_rn(a.x), __int2half_rn(a.y));
    __half2 h1 = __halves2half2(__int2half_rn(a.z), __int2half_rn(a.w));
    __half2 h2 = __halves2half2(__int2half_rn(c.x), __int2half_rn(c.y));
    __half2 h3 = __halves2half2(__int2half_rn(c.z), __int2half_rn(c.w));
    uint4 r;
    r.x = *reinterpret_cast<uint32_t*>(&h0);
    r.y = *reinterpret_cast<uint32_t*>(&h1);
    r.z = *reinterpret_cast<uint32_t*>(&h2);
    r.w = *reinterpret_cast<uint32_t*>(&h3);
    return r;
}

__global__ void __launch_bounds__(256) cvt_xw(
    const float4* __restrict__ x, const int4* __restrict__ wg,
    const int4* __restrict__ wu,
    uint4* __restrict__ ox, uint4* __restrict__ owg, uint4* __restrict__ owu)
{
    int b = blockIdx.x;
    if (b < BX) {
        int i = b * 256 + threadIdx.x;
        float4 a = x[2 * i];
        float4 c = x[2 * i + 1];
        __half2 h0 = __floats2half2_rn(a.x, a.y);
        __half2 h1 = __floats2half2_rn(a.z, a.w);
        __half2 h2 = __floats2half2_rn(c.x, c.y);
        __half2 h3 = __floats2half2_rn(c.z, c.w);
        uint4 r;
        r.x = *reinterpret_cast<uint32_t*>(&h0);
        r.y = *reinterpret_cast<uint32_t*>(&h1);
        r.z = *reinterpret_cast<uint32_t*>(&h2);
        r.w = *reinterpret_cast<uint32_t*>(&h3);
        ox[i] = r;
        return;
    }
    b -= BX;
    if (b < BW) { owg[b * 256 + threadIdx.x] = cvt_i32x8(wg, b * 256 + threadIdx.x); }
    else        { b -= BW; owu[b * 256 + threadIdx.x] = cvt_i32x8(wu, b * 256 + threadIdx.x); }
}

__global__ void __launch_bounds__(256) cvt_wd(const int4* __restrict__ wd,
                                              uint4* __restrict__ owd)
{
    int i = blockIdx.x * 256 + threadIdx.x;
    owd[i] = cvt_i32x8(wd, i);
}

// ============================================================================
// Multistage cp.async + mma.sync GEMM (C = A * B^T), fp16 in, fp32 accum.
//   NB==2 (BN_EACH=128): gate+up share A tile; fused SwiGLU -> fp16 mid.
//   NB==1 (BN_EACH=256): down proj; scaled fp32 out.
// CTA tile: 128(m) x 256(n-total) x 64(k). 256 threads = 8 warps as 2m x 4n
// (minimum crossbar traffic config: A x4 + B x2 redundancy = 128KB/chunk).
// SMEM rows 64 halves = 128B, XOR-swizzled: byte[6:4] ^= row[2:0].
// ============================================================================
template <int NB, int BN_EACH, int STAGES>
__global__ void __launch_bounds__(256, 1) ffn_gemm(
    const __half* __restrict__ A,
    const __half* __restrict__ B0,
    const __half* __restrict__ B1,
    void* __restrict__ outp,
    const float* __restrict__ s0p,
    const float* __restrict__ s1p,
    int K, int ntiles, int ncols)
{
    constexpr int BM = 128, BK = 64;
    constexpr int NTHR = 256;
    constexpr int WN_COLS = BN_EACH / 4;          // warp n-slice per matrix
    constexpr int MI   = 4;                        // m16 groups per warp (64 rows)
    constexpr int NMMA = WN_COLS / 8;              // n8 mmas per warp per matrix
    constexpr int NJ   = NB * (NMMA / 2);
    constexpr int A_BYTES = BM * BK * 2;           // 16384
    constexpr int B_BYTES = BN_EACH * BK * 2;
    constexpr int STAGE_BYTES = A_BYTES + NB * B_BYTES;   // 49152
    constexpr int A_ITERS = (BM * 8) / NTHR;       // 4
    constexpr int B_ITERS = (BN_EACH * 8) / NTHR;  // 4 or 8

    extern __shared__ char smem[];
    const uint32_t sb = smem_to_u32(smem);

    const int tid  = threadIdx.x;
    const int wid  = tid >> 5;
    const int lane = tid & 31;
    const int wm   = wid & 1;       // 0..1 (m)
    const int wn   = wid >> 1;      // 0..3 (n)
    const int quad = lane >> 3;     // 0..3
    const int qr   = lane & 7;

    // L2-friendly tile mapping: groups of 16 m-tiles, n fastest within a group
    constexpr int GM = 16;
    const int tpg = GM * ntiles;
    const int grp = blockIdx.x / tpg;
    const int rem = blockIdx.x % tpg;
    const int mt  = grp * GM + (rem % GM);
    const int nt  = rem / GM;

    const int kch = K / BK;

    float acc[NB][MI][NMMA][4];
#pragma unroll
    for (int g = 0; g < NB; g++)
#pragma unroll
        for (int mi = 0; mi < MI; mi++)
#pragma unroll
            for (int ni = 0; ni < NMMA; ni++)
#pragma unroll
                for (int q = 0; q < 4; q++) acc[g][mi][ni][q] = 0.f;

    // ---- affine loader bases (row stride 32 keeps row&7, so swizzle fixed) --
    const int lrow = tid >> 3;                    // 0..31
    const int lch  = tid & 7;
    const uint32_t ldst = lrow * 128 + ((lch * 16) ^ ((lrow & 7) << 4));
    const __half* aP = A + (size_t)(mt * BM + lrow) * K + lch * 8;
    const __half* bP[2];
    bP[0] = B0 + (size_t)(nt * BN_EACH + lrow) * K + lch * 8;
    bP[1] = B1 + (size_t)(nt * BN_EACH + lrow) * K + lch * 8;
    const size_t rstep = (size_t)32 * K;          // 32 rows forward

    auto load_stage = [&](int kc, int slot) {
        const uint32_t st = sb + slot * STAGE_BYTES + ldst;
        const int k0 = kc * BK;
#pragma unroll
        for (int it = 0; it < A_ITERS; it++)
            cp_async16(st + it * 4096, aP + k0 + it * rstep);
#pragma unroll
        for (int g = 0; g < NB; g++) {
            const __half* bp = bP[g] + k0;
            const uint32_t bbase = st + A_BYTES + g * B_BYTES;
#pragma unroll
            for (int it = 0; it < B_ITERS; it++)
                cp_async16(bbase + it * 4096, bp + it * rstep);
        }
    };

    // ---- prologue: stages 0..S-2 ----
#pragma unroll
    for (int s = 0; s < STAGES - 1; s++) {
        load_stage(s, s);
        CP_COMMIT();
    }

    // ---- main loop: one barrier pair per chunk, prefetch overlapped ----
    for (int kc = 0; kc < kch; kc++) {
        __syncthreads();                 // all warps done reading slot (kc-1)%S
        const int pre = kc + STAGES - 1;
        if (pre < kch) load_stage(pre, pre % STAGES);
        CP_COMMIT();
        cp_wait<STAGES - 1>();           // stage kc resident
        __syncthreads();

        const uint32_t st = sb + (kc % STAGES) * STAGE_BYTES;
#pragma unroll
        for (int ks = 0; ks < 4; ks++) {
            uint32_t fa[MI][4];
#pragma unroll
            for (int mi = 0; mi < MI; mi++) {
                int row  = wm * 64 + mi * 16 + (quad & 1) * 8 + qr;
                int colb = ks * 32 + (quad >> 1) * 16;
                uint32_t ad = st + row * 128 + (colb ^ ((row & 7) << 4));
                ldsm_x4(fa[mi][0], fa[mi][1], fa[mi][2], fa[mi][3], ad);
            }
            uint32_t fb[NJ][4];
#pragma unroll
            for (int g = 0; g < NB; g++)
#pragma unroll
                for (int j = 0; j < NMMA / 2; j++) {
                    int row  = wn * WN_COLS + j * 16 + (quad >> 1) * 8 + qr;
                    int colb = ks * 32 + (quad & 1) * 16;
                    uint32_t bd = st + A_BYTES + g * B_BYTES + row * 128 +
                                  (colb ^ ((row & 7) << 4));
                    int jj = g * (NMMA / 2) + j;
                    ldsm_x4(fb[jj][0], fb[jj][1], fb[jj][2], fb[jj][3], bd);
                }
#pragma unroll
            for (int g = 0; g < NB; g++)
#pragma unroll
                for (int mi = 0; mi < MI; mi++)
#pragma unroll
                    for (int ni = 0; ni < NMMA; ni++)
                        mma16816(acc[g][mi][ni], fa[mi],
                                 &fb[g * (NMMA / 2) + (ni >> 1)][(ni & 1) * 2]);
        }
    }

    // ---- epilogue ----
    const float s0 = *s0p;
    const float s1 = *s1p;
    if (NB == 2) {
        __half* out = (__half*)outp;
#pragma unroll
        for (int mi = 0; mi < MI; mi++)
#pragma unroll
            for (int ni = 0; ni < NMMA; ni++) {
                int row0 = mt * BM + wm * 64 + mi * 16 + (lane >> 2);
                int col  = nt * BN_EACH + wn * WN_COLS + ni * 8 + (lane & 3) * 2;
#pragma unroll
                for (int h = 0; h < 2; h++) {
                    int row = row0 + h * 8;
                    float g0 = s0 * acc[0][mi][ni][2 * h + 0];
                    float g1 = s0 * acc[0][mi][ni][2 * h + 1];
                    float u0 = s1 * acc[1][mi][ni][2 * h + 0];
                    float u1 = s1 * acc[1][mi][ni][2 * h + 1];
                    float r0 = g0 / (1.f + __expf(-g0)) * u0;
                    float r1 = g1 / (1.f + __expf(-g1)) * u1;
                    *(__half2*)(out + (size_t)row * ncols + col) =
                        __floats2half2_rn(r0, r1);
                }
            }
    } else {
        float* out = (float*)outp;
#pragma unroll
        for (int mi = 0; mi < MI; mi++)
#pragma unroll
            for (int ni = 0; ni < NMMA; ni++) {
                int row0 = mt * BM + wm * 64 + mi * 16 + (lane >> 2);
                int col  = nt * BN_EACH + wn * WN_COLS + ni * 8 + (lane & 3) * 2;
#pragma unroll
                for (int h = 0; h < 2; h++) {
                    int row = row0 + h * 8;
                    float2 v;
                    v.x = s0 * acc[0][mi][ni][2 * h + 0];
                    v.y = s0 * acc[0][mi][ni][2 * h + 1];
                    *(float2*)(out + (size_t)row * ncols + col) = v;
                }
            }
    }
}

// ============================================================================
// Host side
// ============================================================================
extern "C" void kernel_launch(void* const* d_in, const int* in_sizes, int n_in,
                              void* d_out, int out_size) {
    const float* x  = (const float*)d_in[0];
    const int*   wg = (const int*)d_in[1];
    const int*   wu = (const int*)d_in[2];
    const int*   wd = (const int*)d_in[3];
    const float* sg = (const float*)d_in[4];
    const float* su = (const float*)d_in[5];
    const float* sd = (const float*)d_in[6];

    void *px, *pwg, *pwu, *pwd, *pmid;
    cudaGetSymbolAddress(&px,  g_x);
    cudaGetSymbolAddress(&pwg, g_wg);
    cudaGetSymbolAddress(&pwu, g_wu);
    cudaGetSymbolAddress(&pwd, g_wd);
    cudaGetSymbolAddress(&pmid, g_mid);

    constexpr int STAGES = 4;
    constexpr int SMEM_BYTES = STAGES * 49152;   // 196608
    cudaFuncSetAttribute(ffn_gemm<2, 128, STAGES>,
                         cudaFuncAttributeMaxDynamicSharedMemorySize, SMEM_BYTES);
    cudaFuncSetAttribute(ffn_gemm<1, 256, STAGES>,
                         cudaFuncAttributeMaxDynamicSharedMemorySize, SMEM_BYTES);

    // Launch 1: convert x + gate/up weights (needed by GEMM1)
    cvt_xw<<<BX + 2 * BW, 256>>>(
        (const float4*)x, (const int4*)wg, (const int4*)wu,
        (uint4*)px, (uint4*)pwg, (uint4*)pwu);

    // Launch 2: GEMM1 fused gate+up+SwiGLU -> g_mid (fp16)
    {
        int mtiles = MROWS / 128;   // 64
        int ntiles = HID / 128;     // 86
        ffn_gemm<2, 128, STAGES><<<mtiles * ntiles, 256, SMEM_BYTES>>>(
            (const __half*)px, (const __half*)pwg, (const __half*)pwu,
            pmid, sg, su, DIMN, ntiles, HID);
    }

    // Launch 3: convert down-proj weights (only needed by GEMM2)
    cvt_wd<<<BW, 256>>>((const int4*)wd, (uint4*)pwd);

    // Launch 4: GEMM2 down projection -> d_out (fp32)
    {
        int mtiles = MROWS / 128;   // 64
        int ntiles = DIMN / 256;    // 16
        ffn_gemm<1, 256, STAGES><<<mtiles * ntiles, 256, SMEM_BYTES>>>(
            (const __half*)pmid, (const __half*)pwd, (const __half*)pwd,
            d_out, sd, sd, HID, ntiles, DIMN);
    }
}

// round 9
// speedup vs baseline: 1.2136x; 1.1026x over previous
#include <cuda_runtime.h>
#include <cuda_fp16.h>
#include <cstdint>

// ============================================================================
// Problem sizes (fixed for this dataset)
// ============================================================================
static constexpr int DIMN  = 4096;
static constexpr int HID   = 11008;
static constexpr int MROWS = 8192;   // B*S = 4*2048

// ============================================================================
// Device scratch (allocation-free rule: __device__ globals)
// ============================================================================
static __device__ __align__(256) __half g_x  [(size_t)MROWS * DIMN];
static __device__ __align__(256) __half g_wg [(size_t)HID   * DIMN];
static __device__ __align__(256) __half g_wu [(size_t)HID   * DIMN];
static __device__ __align__(256) __half g_wd [(size_t)DIMN  * HID ];
static __device__ __align__(256) __half g_mid[(size_t)MROWS * HID ];

// ============================================================================
// PTX helpers — compute_103-safe only (cp.async, ldmatrix, mma.sync.m16n8k16)
// ============================================================================
__device__ __forceinline__ uint32_t smem_to_u32(const void* smem_ptr) {
    uint32_t addr;
    asm("{ .reg .u64 tmp; cvta.to.shared.u64 tmp, %1; cvt.u32.u64 %0, tmp; }"
        : "=r"(addr) : "l"(smem_ptr));
    return addr;
}

__device__ __forceinline__ void cp_async16(uint32_t dst, const void* src) {
    asm volatile("cp.async.cg.shared.global [%0], [%1], 16;\n"
                 :: "r"(dst), "l"(src) : "memory");
}
#define CP_COMMIT() asm volatile("cp.async.commit_group;\n" ::: "memory")
template <int N>
__device__ __forceinline__ void cp_wait() {
    asm volatile("cp.async.wait_group %0;\n" :: "n"(N) : "memory");
}

__device__ __forceinline__ void ldsm_x4(uint32_t& r0, uint32_t& r1,
                                        uint32_t& r2, uint32_t& r3, uint32_t addr) {
    asm volatile("ldmatrix.sync.aligned.m8n8.x4.shared.b16 {%0,%1,%2,%3}, [%4];"
                 : "=r"(r0), "=r"(r1), "=r"(r2), "=r"(r3) : "r"(addr));
}

__device__ __forceinline__ void mma16816(float* c, const uint32_t* a, const uint32_t* b) {
    asm volatile(
        "mma.sync.aligned.m16n8k16.row.col.f32.f16.f16.f32 "
        "{%0,%1,%2,%3}, {%4,%5,%6,%7}, {%8,%9}, {%0,%1,%2,%3};"
        : "+f"(c[0]), "+f"(c[1]), "+f"(c[2]), "+f"(c[3])
        : "r"(a[0]), "r"(a[1]), "r"(a[2]), "r"(a[3]), "r"(b[0]), "r"(b[1]));
}

// ============================================================================
// Converts, split so the ncu capture slot lands on a GEMM:
// order is cvt_xw -> gemm1 -> cvt_wd -> gemm2.
// ============================================================================
static constexpr int N8X = (MROWS * DIMN) / 8;   // 4,194,304 -> 16384 blocks
static constexpr int N8W = (HID * DIMN) / 8;     // 5,636,096 -> 22016 blocks
static constexpr int BX  = N8X / 256;            // 16384
static constexpr int BW  = N8W / 256;            // 22016

__device__ __forceinline__ uint4 cvt_i32x8(const int4* src, int i) {
    int4 a = src[2 * i];
    int4 c = src[2 * i + 1];
    __half2 h0 = __halves2half2(__int2half_rn(a.x), __int2half_rn(a.y));
    __half2 h1 = __halves2half2(__int2half_rn(a.z), __int2half_rn(a.w));
    __half2 h2 = __halves2half2(__int2half_rn(c.x), __int2half_rn(c.y));
    __half2 h3 = __halves2half2(__int2half_rn(c.z), __int2half_rn(c.w));
    uint4 r;
    r.x = *reinterpret_cast<uint32_t*>(&h0);
    r.y = *reinterpret_cast<uint32_t*>(&h1);
    r.z = *reinterpret_cast<uint32_t*>(&h2);
    r.w = *reinterpret_cast<uint32_t*>(&h3);
    return r;
}

__global__ void __launch_bounds__(256) cvt_xw(
    const float4* __restrict__ x, const int4* __restrict__ wg,
    const int4* __restrict__ wu,
    uint4* __restrict__ ox, uint4* __restrict__ owg, uint4* __restrict__ owu)
{
    int b = blockIdx.x;
    if (b < BX) {
        int i = b * 256 + threadIdx.x;
        float4 a = x[2 * i];
        float4 c = x[2 * i + 1];
        __half2 h0 = __floats2half2_rn(a.x, a.y);
        __half2 h1 = __floats2half2_rn(a.z, a.w);
        __half2 h2 = __floats2half2_rn(c.x, c.y);
        __half2 h3 = __floats2half2_rn(c.z, c.w);
        uint4 r;
        r.x = *reinterpret_cast<uint32_t*>(&h0);
        r.y = *reinterpret_cast<uint32_t*>(&h1);
        r.z = *reinterpret_cast<uint32_t*>(&h2);
        r.w = *reinterpret_cast<uint32_t*>(&h3);
        ox[i] = r;
        return;
    }
    b -= BX;
    if (b < BW) { owg[b * 256 + threadIdx.x] = cvt_i32x8(wg, b * 256 + threadIdx.x); }
    else        { b -= BW; owu[b * 256 + threadIdx.x] = cvt_i32x8(wu, b * 256 + threadIdx.x); }
}

__global__ void __launch_bounds__(256) cvt_wd(const int4* __restrict__ wd,
                                              uint4* __restrict__ owd)
{
    int i = blockIdx.x * 256 + threadIdx.x;
    owd[i] = cvt_i32x8(wd, i);
}

// ============================================================================
// Multistage cp.async + mma.sync GEMM (C = A * B^T), fp16 in, fp32 accum.
//   NB==2 (BN_EACH=64):  gate+up share A tile; fused SwiGLU -> fp16 mid.
//   NB==1 (BN_EACH=128): down proj; scaled fp32 out.
// CTA tile: 128(m) x 128(n-total) x 64(k); 256 threads = 8 warps as 2m x 4n.
// OCCUPANCY 2: 3 stages x 32KB = 96KB SMEM/CTA, <=128 regs/thread
// (acc 64 fp32). Two independent CTAs per SM overlap each other's barrier
// and cp.async wait windows -> tensor pipe target 85%+ (was 68.6% at occ 1).
// SMEM rows 64 halves = 128B, XOR-swizzled: byte[6:4] ^= row[2:0].
// ============================================================================
template <int NB, int BN_EACH, int STAGES>
__global__ void __launch_bounds__(256, 2) ffn_gemm(
    const __half* __restrict__ A,
    const __half* __restrict__ B0,
    const __half* __restrict__ B1,
    void* __restrict__ outp,
    const float* __restrict__ s0p,
    const float* __restrict__ s1p,
    int K, int ntiles, int ncols)
{
    constexpr int BM = 128, BK = 64;
    constexpr int NTHR = 256;
    constexpr int WN_COLS = BN_EACH / 4;          // warp n-slice per matrix: 16/32
    constexpr int MI   = 4;                        // m16 groups per warp (64 rows)
    constexpr int NMMA = WN_COLS / 8;              // n8 mmas per warp per matrix: 2/4
    constexpr int NJ   = NB * (NMMA / 2);          // n16 ldsm groups total: 2
    constexpr int A_BYTES = BM * BK * 2;           // 16384
    constexpr int B_BYTES = BN_EACH * BK * 2;      // 8192 or 16384
    constexpr int STAGE_BYTES = A_BYTES + NB * B_BYTES;   // 32768 either way
    constexpr int A_ITERS = (BM * 8) / NTHR;       // 4
    constexpr int B_ITERS = (BN_EACH * 8) / NTHR;  // 2 or 4

    extern __shared__ char smem[];
    const uint32_t sb = smem_to_u32(smem);

    const int tid  = threadIdx.x;
    const int wid  = tid >> 5;
    const int lane = tid & 31;
    const int wm   = wid & 1;       // 0..1 (m)
    const int wn   = wid >> 1;      // 0..3 (n)
    const int quad = lane >> 3;     // 0..3
    const int qr   = lane & 7;

    // L2-friendly tile mapping: groups of 8 m-tiles, n fastest within a group
    constexpr int GM = 8;
    const int tpg = GM * ntiles;
    const int grp = blockIdx.x / tpg;
    const int rem = blockIdx.x % tpg;
    const int mt  = grp * GM + (rem % GM);
    const int nt  = rem / GM;

    const int kch = K / BK;

    float acc[NB][MI][NMMA][4];
#pragma unroll
    for (int g = 0; g < NB; g++)
#pragma unroll
        for (int mi = 0; mi < MI; mi++)
#pragma unroll
            for (int ni = 0; ni < NMMA; ni++)
#pragma unroll
                for (int q = 0; q < 4; q++) acc[g][mi][ni][q] = 0.f;

    // ---- affine loader bases (row stride 32 keeps row&7, so swizzle fixed) --
    const int lrow = tid >> 3;                    // 0..31
    const int lch  = tid & 7;
    const uint32_t ldst = lrow * 128 + ((lch * 16) ^ ((lrow & 7) << 4));
    const __half* aP = A + (size_t)(mt * BM + lrow) * K + lch * 8;
    const __half* bP[2];
    bP[0] = B0 + (size_t)(nt * BN_EACH + lrow) * K + lch * 8;
    bP[1] = B1 + (size_t)(nt * BN_EACH + lrow) * K + lch * 8;
    const size_t rstep = (size_t)32 * K;          // 32 rows forward

    auto load_stage = [&](int kc, int slot) {
        const uint32_t st = sb + slot * STAGE_BYTES + ldst;
        const int k0 = kc * BK;
#pragma unroll
        for (int it = 0; it < A_ITERS; it++)
            cp_async16(st + it * 4096, aP + k0 + it * rstep);
#pragma unroll
        for (int g = 0; g < NB; g++) {
            const __half* bp = bP[g] + k0;
            const uint32_t bbase = st + A_BYTES + g * B_BYTES;
#pragma unroll
            for (int it = 0; it < B_ITERS; it++)
                cp_async16(bbase + it * 4096, bp + it * rstep);
        }
    };

    // ---- prologue: stages 0..S-2 ----
#pragma unroll
    for (int s = 0; s < STAGES - 1; s++) {
        load_stage(s, s);
        CP_COMMIT();
    }

    // ---- main loop: prefetch overlapped with wait ----
    for (int kc = 0; kc < kch; kc++) {
        __syncthreads();                 // all warps done reading slot (kc-1)%S
        const int pre = kc + STAGES - 1;
        if (pre < kch) load_stage(pre, pre % STAGES);
        CP_COMMIT();
        cp_wait<STAGES - 1>();           // stage kc resident
        __syncthreads();

        const uint32_t st = sb + (kc % STAGES) * STAGE_BYTES;
#pragma unroll
        for (int ks = 0; ks < 4; ks++) {
            uint32_t fa[MI][4];
#pragma unroll
            for (int mi = 0; mi < MI; mi++) {
                int row  = wm * 64 + mi * 16 + (quad & 1) * 8 + qr;
                int colb = ks * 32 + (quad >> 1) * 16;
                uint32_t ad = st + row * 128 + (colb ^ ((row & 7) << 4));
                ldsm_x4(fa[mi][0], fa[mi][1], fa[mi][2], fa[mi][3], ad);
            }
            uint32_t fb[NJ][4];
#pragma unroll
            for (int g = 0; g < NB; g++)
#pragma unroll
                for (int j = 0; j < NMMA / 2; j++) {
                    int row  = wn * WN_COLS + j * 16 + (quad >> 1) * 8 + qr;
                    int colb = ks * 32 + (quad & 1) * 16;
                    uint32_t bd = st + A_BYTES + g * B_BYTES + row * 128 +
                                  (colb ^ ((row & 7) << 4));
                    int jj = g * (NMMA / 2) + j;
                    ldsm_x4(fb[jj][0], fb[jj][1], fb[jj][2], fb[jj][3], bd);
                }
#pragma unroll
            for (int g = 0; g < NB; g++)
#pragma unroll
                for (int mi = 0; mi < MI; mi++)
#pragma unroll
                    for (int ni = 0; ni < NMMA; ni++)
                        mma16816(acc[g][mi][ni], fa[mi],
                                 &fb[g * (NMMA / 2) + (ni >> 1)][(ni & 1) * 2]);
        }
    }

    // ---- epilogue ----
    const float s0 = *s0p;
    const float s1 = *s1p;
    if (NB == 2) {
        __half* out = (__half*)outp;
#pragma unroll
        for (int mi = 0; mi < MI; mi++)
#pragma unroll
            for (int ni = 0; ni < NMMA; ni++) {
                int row0 = mt * BM + wm * 64 + mi * 16 + (lane >> 2);
                int col  = nt * BN_EACH + wn * WN_COLS + ni * 8 + (lane & 3) * 2;
#pragma unroll
                for (int h = 0; h < 2; h++) {
                    int row = row0 + h * 8;
                    float g0 = s0 * acc[0][mi][ni][2 * h + 0];
                    float g1 = s0 * acc[0][mi][ni][2 * h + 1];
                    float u0 = s1 * acc[1][mi][ni][2 * h + 0];
                    float u1 = s1 * acc[1][mi][ni][2 * h + 1];
                    float r0 = g0 / (1.f + __expf(-g0)) * u0;
                    float r1 = g1 / (1.f + __expf(-g1)) * u1;
                    *(__half2*)(out + (size_t)row * ncols + col) =
                        __floats2half2_rn(r0, r1);
                }
            }
    } else {
        float* out = (float*)outp;
#pragma unroll
        for (int mi = 0; mi < MI; mi++)
#pragma unroll
            for (int ni = 0; ni < NMMA; ni++) {
                int row0 = mt * BM + wm * 64 + mi * 16 + (lane >> 2);
                int col  = nt * BN_EACH + wn * WN_COLS + ni * 8 + (lane & 3) * 2;
#pragma unroll
                for (int h = 0; h < 2; h++) {
                    int row = row0 + h * 8;
                    float2 v;
                    v.x = s0 * acc[0][mi][ni][2 * h + 0];
                    v.y = s0 * acc[0][mi][ni][2 * h + 1];
                    *(float2*)(out + (size_t)row * ncols + col) = v;
                }
            }
    }
}

// ============================================================================
// Host side
// ============================================================================
extern "C" void kernel_launch(void* const* d_in, const int* in_sizes, int n_in,
                              void* d_out, int out_size) {
    const float* x  = (const float*)d_in[0];
    const int*   wg = (const int*)d_in[1];
    const int*   wu = (const int*)d_in[2];
    const int*   wd = (const int*)d_in[3];
    const float* sg = (const float*)d_in[4];
    const float* su = (const float*)d_in[5];
    const float* sd = (const float*)d_in[6];

    void *px, *pwg, *pwu, *pwd, *pmid;
    cudaGetSymbolAddress(&px,  g_x);
    cudaGetSymbolAddress(&pwg, g_wg);
    cudaGetSymbolAddress(&pwu, g_wu);
    cudaGetSymbolAddress(&pwd, g_wd);
    cudaGetSymbolAddress(&pmid, g_mid);

    constexpr int STAGES = 3;
    constexpr int SMEM_BYTES = STAGES * 32768;   // 98304 per CTA -> 2 CTAs/SM
    cudaFuncSetAttribute(ffn_gemm<2, 64, STAGES>,
                         cudaFuncAttributeMaxDynamicSharedMemorySize, SMEM_BYTES);
    cudaFuncSetAttribute(ffn_gemm<1, 128, STAGES>,
                         cudaFuncAttributeMaxDynamicSharedMemorySize, SMEM_BYTES);

    // Launch 1: convert x + gate/up weights (needed by GEMM1)
    cvt_xw<<<BX + 2 * BW, 256>>>(
        (const float4*)x, (const int4*)wg, (const int4*)wu,
        (uint4*)px, (uint4*)pwg, (uint4*)pwu);

    // Launch 2: GEMM1 fused gate+up+SwiGLU -> g_mid (fp16). Tile 128 x 64x2.
    {
        int mtiles = MROWS / 128;   // 64
        int ntiles = HID / 64;      // 172
        ffn_gemm<2, 64, STAGES><<<mtiles * ntiles, 256, SMEM_BYTES>>>(
            (const __half*)px, (const __half*)pwg, (const __half*)pwu,
            pmid, sg, su, DIMN, ntiles, HID);
    }

    // Launch 3: convert down-proj weights (only needed by GEMM2)
    cvt_wd<<<BW, 256>>>((const int4*)wd, (uint4*)pwd);

    // Launch 4: GEMM2 down projection -> d_out (fp32). Tile 128 x 128.
    {
        int mtiles = MROWS / 128;   // 64
        int ntiles = DIMN / 128;    // 32
        ffn_gemm<1, 128, STAGES><<<mtiles * ntiles, 256, SMEM_BYTES>>>(
            (const __half*)pmid, (const __half*)pwd, (const __half*)pwd,
            d_out, sd, sd, HID, ntiles, DIMN);
    }
}

// round 10
// speedup vs baseline: 1.2292x; 1.0128x over previous
#include <cuda_runtime.h>
#include <cuda_fp16.h>
#include <cstdint>

// ============================================================================
// Problem sizes (fixed for this dataset)
// ============================================================================
static constexpr int DIMN  = 4096;
static constexpr int HID   = 11008;
static constexpr int MROWS = 8192;   // B*S = 4*2048

// ============================================================================
// Device scratch (allocation-free rule: __device__ globals)
// ============================================================================
static __device__ __align__(256) __half g_x  [(size_t)MROWS * DIMN];
static __device__ __align__(256) __half g_wg [(size_t)HID   * DIMN];
static __device__ __align__(256) __half g_wu [(size_t)HID   * DIMN];
static __device__ __align__(256) __half g_wd [(size_t)DIMN  * HID ];
static __device__ __align__(256) __half g_mid[(size_t)MROWS * HID ];

// ============================================================================
// PTX helpers — compute_103-safe only (cp.async, ldmatrix, mma.sync.m16n8k16)
// ============================================================================
__device__ __forceinline__ uint32_t smem_to_u32(const void* smem_ptr) {
    uint32_t addr;
    asm("{ .reg .u64 tmp; cvta.to.shared.u64 tmp, %1; cvt.u32.u64 %0, tmp; }"
        : "=r"(addr) : "l"(smem_ptr));
    return addr;
}

__device__ __forceinline__ void cp_async16(uint32_t dst, const void* src) {
    asm volatile("cp.async.cg.shared.global [%0], [%1], 16;\n"
                 :: "r"(dst), "l"(src) : "memory");
}
#define CP_COMMIT() asm volatile("cp.async.commit_group;\n" ::: "memory")
template <int N>
__device__ __forceinline__ void cp_wait() {
    asm volatile("cp.async.wait_group %0;\n" :: "n"(N) : "memory");
}

__device__ __forceinline__ void ldsm_x4(uint32_t& r0, uint32_t& r1,
                                        uint32_t& r2, uint32_t& r3, uint32_t addr) {
    asm volatile("ldmatrix.sync.aligned.m8n8.x4.shared.b16 {%0,%1,%2,%3}, [%4];"
                 : "=r"(r0), "=r"(r1), "=r"(r2), "=r"(r3) : "r"(addr));
}

__device__ __forceinline__ void mma16816(float* c, const uint32_t* a, const uint32_t* b) {
    asm volatile(
        "mma.sync.aligned.m16n8k16.row.col.f32.f16.f16.f32 "
        "{%0,%1,%2,%3}, {%4,%5,%6,%7}, {%8,%9}, {%0,%1,%2,%3};"
        : "+f"(c[0]), "+f"(c[1]), "+f"(c[2]), "+f"(c[3])
        : "r"(a[0]), "r"(a[1]), "r"(a[2]), "r"(a[3]), "r"(b[0]), "r"(b[1]));
}

// ============================================================================
// Converts, split so the ncu capture slot lands on a GEMM:
// order is cvt_xw -> gemm1 -> cvt_wd -> gemm2.
// ============================================================================
static constexpr int N8X = (MROWS * DIMN) / 8;   // 4,194,304 -> 16384 blocks
static constexpr int N8W = (HID * DIMN) / 8;     // 5,636,096 -> 22016 blocks
static constexpr int BX  = N8X / 256;            // 16384
static constexpr int BW  = N8W / 256;            // 22016

__device__ __forceinline__ uint4 cvt_i32x8(const int4* src, int i) {
    int4 a = src[2 * i];
    int4 c = src[2 * i + 1];
    __half2 h0 = __halves2half2(__int2half_rn(a.x), __int2half_rn(a.y));
    __half2 h1 = __halves2half2(__int2half_rn(a.z), __int2half_rn(a.w));
    __half2 h2 = __halves2half2(__int2half_rn(c.x), __int2half_rn(c.y));
    __half2 h3 = __halves2half2(__int2half_rn(c.z), __int2half_rn(c.w));
    uint4 r;
    r.x = *reinterpret_cast<uint32_t*>(&h0);
    r.y = *reinterpret_cast<uint32_t*>(&h1);
    r.z = *reinterpret_cast<uint32_t*>(&h2);
    r.w = *reinterpret_cast<uint32_t*>(&h3);
    return r;
}

__global__ void __launch_bounds__(256) cvt_xw(
    const float4* __restrict__ x, const int4* __restrict__ wg,
    const int4* __restrict__ wu,
    uint4* __restrict__ ox, uint4* __restrict__ owg, uint4* __restrict__ owu)
{
    int b = blockIdx.x;
    if (b < BX) {
        int i = b * 256 + threadIdx.x;
        float4 a = x[2 * i];
        float4 c = x[2 * i + 1];
        __half2 h0 = __floats2half2_rn(a.x, a.y);
        __half2 h1 = __floats2half2_rn(a.z, a.w);
        __half2 h2 = __floats2half2_rn(c.x, c.y);
        __half2 h3 = __floats2half2_rn(c.z, c.w);
        uint4 r;
        r.x = *reinterpret_cast<uint32_t*>(&h0);
        r.y = *reinterpret_cast<uint32_t*>(&h1);
        r.z = *reinterpret_cast<uint32_t*>(&h2);
        r.w = *reinterpret_cast<uint32_t*>(&h3);
        ox[i] = r;
        return;
    }
    b -= BX;
    if (b < BW) { owg[b * 256 + threadIdx.x] = cvt_i32x8(wg, b * 256 + threadIdx.x); }
    else        { b -= BW; owu[b * 256 + threadIdx.x] = cvt_i32x8(wu, b * 256 + threadIdx.x); }
}

__global__ void __launch_bounds__(256) cvt_wd(const int4* __restrict__ wd,
                                              uint4* __restrict__ owd)
{
    int i = blockIdx.x * 256 + threadIdx.x;
    owd[i] = cvt_i32x8(wd, i);
}

// ============================================================================
// Multistage cp.async + mma.sync GEMM (C = A * B^T), fp16 in, fp32 accum.
//   NB==2 (BN_EACH=64):  gate+up share A tile; fused SwiGLU -> fp16 mid.
//   NB==1 (BN_EACH=128): down proj; scaled fp32 out.
// CTA tile: 128(m) x 128(n-total) x 64(k); 256 threads = 8 warps as 2m x 4n.
// OCCUPANCY 2 (3 stages x 32KB = 96KB SMEM/CTA, <=128 regs).
// Canonical single-sync chunk: wait<S-2> -> sync -> [ks loop: ldsm ->
// 2 cp.asyncs of next stage -> mma] -> commit. Next-stage loads are spread
// across the MMA stream so the LSU burst is covered by tensor work
// (was: serialized burst at chunk top while tensor idled -> 72% tensor).
// SMEM rows 64 halves = 128B, XOR-swizzled: byte[6:4] ^= row[2:0].
// ============================================================================
template <int NB, int BN_EACH, int STAGES>
__global__ void __launch_bounds__(256, 2) ffn_gemm(
    const __half* __restrict__ A,
    const __half* __restrict__ B0,
    const __half* __restrict__ B1,
    void* __restrict__ outp,
    const float* __restrict__ s0p,
    const float* __restrict__ s1p,
    int K, int ntiles, int ncols)
{
    constexpr int BM = 128, BK = 64;
    constexpr int NTHR = 256;
    constexpr int WN_COLS = BN_EACH / 4;          // warp n-slice per matrix: 16/32
    constexpr int MI   = 4;                        // m16 groups per warp (64 rows)
    constexpr int NMMA = WN_COLS / 8;              // n8 mmas per warp per matrix: 2/4
    constexpr int NJ   = NB * (NMMA / 2);          // n16 ldsm groups total: 2
    constexpr int A_BYTES = BM * BK * 2;           // 16384
    constexpr int B_BYTES = BN_EACH * BK * 2;      // 8192 or 16384
    constexpr int STAGE_BYTES = A_BYTES + NB * B_BYTES;   // 32768 either way
    constexpr int A_ITERS = (BM * 8) / NTHR;       // 4
    constexpr int B_ITERS = (BN_EACH * 8) / NTHR;  // 2 or 4 (NB*B_ITERS == 4)

    extern __shared__ char smem[];
    const uint32_t sb = smem_to_u32(smem);

    const int tid  = threadIdx.x;
    const int wid  = tid >> 5;
    const int lane = tid & 31;
    const int wm   = wid & 1;       // 0..1 (m)
    const int wn   = wid >> 1;      // 0..3 (n)
    const int quad = lane >> 3;     // 0..3
    const int qr   = lane & 7;

    // L2-friendly tile mapping: groups of 8 m-tiles, n fastest within a group
    constexpr int GM = 8;
    const int tpg = GM * ntiles;
    const int grp = blockIdx.x / tpg;
    const int rem = blockIdx.x % tpg;
    const int mt  = grp * GM + (rem % GM);
    const int nt  = rem / GM;

    const int kch = K / BK;

    float acc[NB][MI][NMMA][4];
#pragma unroll
    for (int g = 0; g < NB; g++)
#pragma unroll
        for (int mi = 0; mi < MI; mi++)
#pragma unroll
            for (int ni = 0; ni < NMMA; ni++)
#pragma unroll
                for (int q = 0; q < 4; q++) acc[g][mi][ni][q] = 0.f;

    // ---- affine loader bases (row stride 32 keeps row&7, so swizzle fixed) --
    const int lrow = tid >> 3;                    // 0..31
    const int lch  = tid & 7;
    const uint32_t ldst = lrow * 128 + ((lch * 16) ^ ((lrow & 7) << 4));
    const __half* aP = A + (size_t)(mt * BM + lrow) * K + lch * 8;
    const __half* bP[2];
    bP[0] = B0 + (size_t)(nt * BN_EACH + lrow) * K + lch * 8;
    bP[1] = B1 + (size_t)(nt * BN_EACH + lrow) * K + lch * 8;
    const size_t rstep = (size_t)32 * K;          // 32 rows forward

    // full-stage load (prologue only)
    auto load_stage = [&](int kc, int slot) {
        const uint32_t st = sb + slot * STAGE_BYTES + ldst;
        const int k0 = kc * BK;
#pragma unroll
        for (int it = 0; it < A_ITERS; it++)
            cp_async16(st + it * 4096, aP + k0 + it * rstep);
#pragma unroll
        for (int g = 0; g < NB; g++) {
            const __half* bp = bP[g] + k0;
            const uint32_t bbase = st + A_BYTES + g * B_BYTES;
#pragma unroll
            for (int it = 0; it < B_ITERS; it++)
                cp_async16(bbase + it * 4096, bp + it * rstep);
        }
    };

    // quarter-stage load: part p in 0..3 issues 1 A op + 1 B op
    auto load_part = [&](int kc, int slot, int p) {
        const uint32_t st = sb + slot * STAGE_BYTES + ldst;
        const int k0 = kc * BK;
        cp_async16(st + p * 4096, aP + k0 + p * rstep);
        if (NB == 2) {
            const int g  = p >> 1;
            const int it = p & 1;
            cp_async16(st + A_BYTES + g * B_BYTES + it * 4096,
                       bP[g] + k0 + it * rstep);
        } else {
            cp_async16(st + A_BYTES + p * 4096, bP[0] + k0 + p * rstep);
        }
    };

    // ---- prologue: stages 0..S-2, one commit group per stage ----
#pragma unroll
    for (int s = 0; s < STAGES - 1; s++) {
        load_stage(s, s);
        CP_COMMIT();
    }

    // ---- main loop: ONE sync per chunk; next-stage loads interleaved ----
    for (int kc = 0; kc < kch; kc++) {
        cp_wait<STAGES - 2>();           // stage kc resident
        __syncthreads();                 // + all warps done reading slot (kc-1)%S

        const int pre = kc + STAGES - 1;
        const bool do_pre = pre < kch;
        const int preslot = pre % STAGES;   // == (kc-1)%S, safe to overwrite

        const uint32_t st = sb + (kc % STAGES) * STAGE_BYTES;
#pragma unroll
        for (int ks = 0; ks < 4; ks++) {
            uint32_t fa[MI][4];
#pragma unroll
            for (int mi = 0; mi < MI; mi++) {
                int row  = wm * 64 + mi * 16 + (quad & 1) * 8 + qr;
                int colb = ks * 32 + (quad >> 1) * 16;
                uint32_t ad = st + row * 128 + (colb ^ ((row & 7) << 4));
                ldsm_x4(fa[mi][0], fa[mi][1], fa[mi][2], fa[mi][3], ad);
            }
            uint32_t fb[NJ][4];
#pragma unroll
            for (int g = 0; g < NB; g++)
#pragma unroll
                for (int j = 0; j < NMMA / 2; j++) {
                    int row  = wn * WN_COLS + j * 16 + (quad >> 1) * 8 + qr;
                    int colb = ks * 32 + (quad & 1) * 16;
                    uint32_t bd = st + A_BYTES + g * B_BYTES + row * 128 +
                                  (colb ^ ((row & 7) << 4));
                    int jj = g * (NMMA / 2) + j;
                    ldsm_x4(fb[jj][0], fb[jj][1], fb[jj][2], fb[jj][3], bd);
                }
            if (do_pre) load_part(pre, preslot, ks);   // 2 cp.asyncs amid MMAs
#pragma unroll
            for (int g = 0; g < NB; g++)
#pragma unroll
                for (int mi = 0; mi < MI; mi++)
#pragma unroll
                    for (int ni = 0; ni < NMMA; ni++)
                        mma16816(acc[g][mi][ni], fa[mi],
                                 &fb[g * (NMMA / 2) + (ni >> 1)][(ni & 1) * 2]);
        }
        CP_COMMIT();                     // one group per chunk (may be empty)
    }

    // ---- epilogue ----
    const float s0 = *s0p;
    const float s1 = *s1p;
    if (NB == 2) {
        __half* out = (__half*)outp;
#pragma unroll
        for (int mi = 0; mi < MI; mi++)
#pragma unroll
            for (int ni = 0; ni < NMMA; ni++) {
                int row0 = mt * BM + wm * 64 + mi * 16 + (lane >> 2);
                int col  = nt * BN_EACH + wn * WN_COLS + ni * 8 + (lane & 3) * 2;
#pragma unroll
                for (int h = 0; h < 2; h++) {
                    int row = row0 + h * 8;
                    float g0 = s0 * acc[0][mi][ni][2 * h + 0];
                    float g1 = s0 * acc[0][mi][ni][2 * h + 1];
                    float u0 = s1 * acc[1][mi][ni][2 * h + 0];
                    float u1 = s1 * acc[1][mi][ni][2 * h + 1];
                    float r0 = g0 / (1.f + __expf(-g0)) * u0;
                    float r1 = g1 / (1.f + __expf(-g1)) * u1;
                    *(__half2*)(out + (size_t)row * ncols + col) =
                        __floats2half2_rn(r0, r1);
                }
            }
    } else {
        float* out = (float*)outp;
#pragma unroll
        for (int mi = 0; mi < MI; mi++)
#pragma unroll
            for (int ni = 0; ni < NMMA; ni++) {
                int row0 = mt * BM + wm * 64 + mi * 16 + (lane >> 2);
                int col  = nt * BN_EACH + wn * WN_COLS + ni * 8 + (lane & 3) * 2;
#pragma unroll
                for (int h = 0; h < 2; h++) {
                    int row = row0 + h * 8;
                    float2 v;
                    v.x = s0 * acc[0][mi][ni][2 * h + 0];
                    v.y = s0 * acc[0][mi][ni][2 * h + 1];
                    *(float2*)(out + (size_t)row * ncols + col) = v;
                }
            }
    }
}

// ============================================================================
// Host side
// ============================================================================
extern "C" void kernel_launch(void* const* d_in, const int* in_sizes, int n_in,
                              void* d_out, int out_size) {
    const float* x  = (const float*)d_in[0];
    const int*   wg = (const int*)d_in[1];
    const int*   wu = (const int*)d_in[2];
    const int*   wd = (const int*)d_in[3];
    const float* sg = (const float*)d_in[4];
    const float* su = (const float*)d_in[5];
    const float* sd = (const float*)d_in[6];

    void *px, *pwg, *pwu, *pwd, *pmid;
    cudaGetSymbolAddress(&px,  g_x);
    cudaGetSymbolAddress(&pwg, g_wg);
    cudaGetSymbolAddress(&pwu, g_wu);
    cudaGetSymbolAddress(&pwd, g_wd);
    cudaGetSymbolAddress(&pmid, g_mid);

    constexpr int STAGES = 3;
    constexpr int SMEM_BYTES = STAGES * 32768;   // 98304 per CTA -> 2 CTAs/SM
    cudaFuncSetAttribute(ffn_gemm<2, 64, STAGES>,
                         cudaFuncAttributeMaxDynamicSharedMemorySize, SMEM_BYTES);
    cudaFuncSetAttribute(ffn_gemm<1, 128, STAGES>,
                         cudaFuncAttributeMaxDynamicSharedMemorySize, SMEM_BYTES);

    // Launch 1: convert x + gate/up weights (needed by GEMM1)
    cvt_xw<<<BX + 2 * BW, 256>>>(
        (const float4*)x, (const int4*)wg, (const int4*)wu,
        (uint4*)px, (uint4*)pwg, (uint4*)pwu);

    // Launch 2: GEMM1 fused gate+up+SwiGLU -> g_mid (fp16). Tile 128 x 64x2.
    {
        int mtiles = MROWS / 128;   // 64
        int ntiles = HID / 64;      // 172
        ffn_gemm<2, 64, STAGES><<<mtiles * ntiles, 256, SMEM_BYTES>>>(
            (const __half*)px, (const __half*)pwg, (const __half*)pwu,
            pmid, sg, su, DIMN, ntiles, HID);
    }

    // Launch 3: convert down-proj weights (only needed by GEMM2)
    cvt_wd<<<BW, 256>>>((const int4*)wd, (uint4*)pwd);

    // Launch 4: GEMM2 down projection -> d_out (fp32). Tile 128 x 128.
    {
        int mtiles = MROWS / 128;   // 64
        int ntiles = DIMN / 128;    // 32
        ffn_gemm<1, 128, STAGES><<<mtiles * ntiles, 256, SMEM_BYTES>>>(
            (const __half*)pmid, (const __half*)pwd, (const __half*)pwd,
            d_out, sd, sd, HID, ntiles, DIMN);
    }
}

// round 11
// speedup vs baseline: 1.2313x; 1.0017x over previous
#include <cuda_runtime.h>
#include <cuda_fp16.h>
#include <cstdint>

// ============================================================================
// Problem sizes (fixed for this dataset)
// ============================================================================
static constexpr int DIMN  = 4096;
static constexpr int HID   = 11008;
static constexpr int MROWS = 8192;   // B*S = 4*2048

// ============================================================================
// Device scratch (allocation-free rule: __device__ globals)
// ============================================================================
static __device__ __align__(256) __half g_x  [(size_t)MROWS * DIMN];
static __device__ __align__(256) __half g_wg [(size_t)HID   * DIMN];
static __device__ __align__(256) __half g_wu [(size_t)HID   * DIMN];
static __device__ __align__(256) __half g_wd [(size_t)DIMN  * HID ];
static __device__ __align__(256) __half g_mid[(size_t)MROWS * HID ];

// ============================================================================
// PTX helpers — compute_103-safe only (cp.async, ldmatrix, mma.sync.m16n8k16)
// ============================================================================
__device__ __forceinline__ uint32_t smem_to_u32(const void* smem_ptr) {
    uint32_t addr;
    asm("{ .reg .u64 tmp; cvta.to.shared.u64 tmp, %1; cvt.u32.u64 %0, tmp; }"
        : "=r"(addr) : "l"(smem_ptr));
    return addr;
}

__device__ __forceinline__ void cp_async16(uint32_t dst, const void* src) {
    asm volatile("cp.async.cg.shared.global [%0], [%1], 16;\n"
                 :: "r"(dst), "l"(src) : "memory");
}
#define CP_COMMIT() asm volatile("cp.async.commit_group;\n" ::: "memory")
template <int N>
__device__ __forceinline__ void cp_wait() {
    asm volatile("cp.async.wait_group %0;\n" :: "n"(N) : "memory");
}

__device__ __forceinline__ void ldsm_x4(uint32_t& r0, uint32_t& r1,
                                        uint32_t& r2, uint32_t& r3, uint32_t addr) {
    asm volatile("ldmatrix.sync.aligned.m8n8.x4.shared.b16 {%0,%1,%2,%3}, [%4];"
                 : "=r"(r0), "=r"(r1), "=r"(r2), "=r"(r3) : "r"(addr));
}

__device__ __forceinline__ void mma16816(float* c, const uint32_t* a, const uint32_t* b) {
    asm volatile(
        "mma.sync.aligned.m16n8k16.row.col.f32.f16.f16.f32 "
        "{%0,%1,%2,%3}, {%4,%5,%6,%7}, {%8,%9}, {%0,%1,%2,%3};"
        : "+f"(c[0]), "+f"(c[1]), "+f"(c[2]), "+f"(c[3])
        : "r"(a[0]), "r"(a[1]), "r"(a[2]), "r"(a[3]), "r"(b[0]), "r"(b[1]));
}

// ============================================================================
// Merged dequant/convert: one launch (launch stream = [cvt, gemm1, gemm2]
// repeating, so the fixed ncu slot still lands on a GEMM).
// ============================================================================
static constexpr int N8X = (MROWS * DIMN) / 8;   // 4,194,304 -> 16384 blocks
static constexpr int N8W = (HID * DIMN) / 8;     // 5,636,096 -> 22016 blocks
static constexpr int BX  = N8X / 256;            // 16384
static constexpr int BW  = N8W / 256;            // 22016

__global__ void __launch_bounds__(256) cvt_all(
    const float4* __restrict__ x, const int4* __restrict__ wg,
    const int4* __restrict__ wu, const int4* __restrict__ wd,
    uint4* __restrict__ ox, uint4* __restrict__ owg,
    uint4* __restrict__ owu, uint4* __restrict__ owd)
{
    int b = blockIdx.x;
    if (b < BX) {
        int i = b * 256 + threadIdx.x;
        float4 a = x[2 * i];
        float4 c = x[2 * i + 1];
        __half2 h0 = __floats2half2_rn(a.x, a.y);
        __half2 h1 = __floats2half2_rn(a.z, a.w);
        __half2 h2 = __floats2half2_rn(c.x, c.y);
        __half2 h3 = __floats2half2_rn(c.z, c.w);
        uint4 r;
        r.x = *reinterpret_cast<uint32_t*>(&h0);
        r.y = *reinterpret_cast<uint32_t*>(&h1);
        r.z = *reinterpret_cast<uint32_t*>(&h2);
        r.w = *reinterpret_cast<uint32_t*>(&h3);
        ox[i] = r;
        return;
    }
    b -= BX;
    const int4* src;
    uint4* dst;
    if (b < BW)            { src = wg; dst = owg; }
    else if (b < 2 * BW)   { src = wu; dst = owu; b -= BW; }
    else                   { src = wd; dst = owd; b -= 2 * BW; }
    int i = b * 256 + threadIdx.x;
    int4 a = src[2 * i];
    int4 c = src[2 * i + 1];
    __half2 h0 = __halves2half2(__int2half_rn(a.x), __int2half_rn(a.y));
    __half2 h1 = __halves2half2(__int2half_rn(a.z), __int2half_rn(a.w));
    __half2 h2 = __halves2half2(__int2half_rn(c.x), __int2half_rn(c.y));
    __half2 h3 = __halves2half2(__int2half_rn(c.z), __int2half_rn(c.w));
    uint4 r;
    r.x = *reinterpret_cast<uint32_t*>(&h0);
    r.y = *reinterpret_cast<uint32_t*>(&h1);
    r.z = *reinterpret_cast<uint32_t*>(&h2);
    r.w = *reinterpret_cast<uint32_t*>(&h3);
    dst[i] = r;
}

// ============================================================================
// Multistage cp.async + mma.sync GEMM (C = A * B^T), fp16 in, fp32 accum.
//   NB==2 (BN_EACH=64):  gate+up share A tile; fused SwiGLU -> fp16 mid.
//   NB==1 (BN_EACH=128): down proj; scaled fp32 out.
// CTA tile: 128(m) x 128(n-total) x 64(k); 256 threads = 8 warps as 2m x 4n.
// OCCUPANCY 2 (3 stages x 32KB = 96KB SMEM/CTA, <=128 regs). This is the
// crossbar-traffic-minimal config: 96KB LDSM reads + 32KB STS per 1M MACs,
// co-bound with the tensor pipe (~74%). Single-sync chunk with next-stage
// loads interleaved into the MMA stream.
// LDSM addressing hoisted: for this layout row&7 == qr for every fragment
// row, so the SW128 XOR splits into disjoint bitfields:
//   addr = st + base[frag] + kxo[ks],   kxo[ks] = (ks*32) ^ ((qr<<4)&0x60)
// (base folds row*128 + (c0 ^ ((qr<<4)&0x10))). One IADD3 per LDSM.
// ============================================================================
template <int NB, int BN_EACH, int STAGES>
__global__ void __launch_bounds__(256, 2) ffn_gemm(
    const __half* __restrict__ A,
    const __half* __restrict__ B0,
    const __half* __restrict__ B1,
    void* __restrict__ outp,
    const float* __restrict__ s0p,
    const float* __restrict__ s1p,
    int K, int ntiles, int ncols)
{
    constexpr int BM = 128, BK = 64;
    constexpr int NTHR = 256;
    constexpr int WN_COLS = BN_EACH / 4;          // warp n-slice per matrix: 16/32
    constexpr int MI   = 4;                        // m16 groups per warp (64 rows)
    constexpr int NMMA = WN_COLS / 8;              // n8 mmas per warp per matrix: 2/4
    constexpr int NJ   = NB * (NMMA / 2);          // n16 ldsm groups total: 2
    constexpr int A_BYTES = BM * BK * 2;           // 16384
    constexpr int B_BYTES = BN_EACH * BK * 2;      // 8192 or 16384
    constexpr int STAGE_BYTES = A_BYTES + NB * B_BYTES;   // 32768 either way
    constexpr int A_ITERS = (BM * 8) / NTHR;       // 4
    constexpr int B_ITERS = (BN_EACH * 8) / NTHR;  // 2 or 4 (NB*B_ITERS == 4)

    extern __shared__ char smem[];
    const uint32_t sb = smem_to_u32(smem);

    const int tid  = threadIdx.x;
    const int wid  = tid >> 5;
    const int lane = tid & 31;
    const int wm   = wid & 1;       // 0..1 (m)
    const int wn   = wid >> 1;      // 0..3 (n)
    const int quad = lane >> 3;     // 0..3
    const int qr   = lane & 7;

    // L2-friendly tile mapping: groups of 8 m-tiles, n fastest within a group
    constexpr int GM = 8;
    const int tpg = GM * ntiles;
    const int grp = blockIdx.x / tpg;
    const int rem = blockIdx.x % tpg;
    const int mt  = grp * GM + (rem % GM);
    const int nt  = rem / GM;

    const int kch = K / BK;

    float acc[NB][MI][NMMA][4];
#pragma unroll
    for (int g = 0; g < NB; g++)
#pragma unroll
        for (int mi = 0; mi < MI; mi++)
#pragma unroll
            for (int ni = 0; ni < NMMA; ni++)
#pragma unroll
                for (int q = 0; q < 4; q++) acc[g][mi][ni][q] = 0.f;

    // ---- hoisted LDSM address components ----
    const uint32_t xr   = (uint32_t)(qr << 4);
    const uint32_t xr60 = xr & 0x60;
    const uint32_t xr10 = xr & 0x10;
    uint32_t kxo[4];
#pragma unroll
    for (int ks = 0; ks < 4; ks++) kxo[ks] = ((uint32_t)(ks * 32)) ^ xr60;

    uint32_t baseA[MI];
#pragma unroll
    for (int mi = 0; mi < MI; mi++) {
        int row = wm * 64 + mi * 16 + (quad & 1) * 8 + qr;          // row&7 == qr
        baseA[mi] = (uint32_t)(row * 128) + (((uint32_t)((quad >> 1) * 16)) ^ xr10);
    }
    uint32_t baseB[NJ];
#pragma unroll
    for (int g = 0; g < NB; g++)
#pragma unroll
        for (int j = 0; j < NMMA / 2; j++) {
            int row = wn * WN_COLS + j * 16 + (quad >> 1) * 8 + qr; // row&7 == qr
            baseB[g * (NMMA / 2) + j] =
                (uint32_t)(A_BYTES + g * B_BYTES + row * 128) +
                (((uint32_t)((quad & 1) * 16)) ^ xr10);
        }

    // ---- affine loader bases (row stride 32 keeps row&7, so swizzle fixed) --
    const int lrow = tid >> 3;                    // 0..31
    const int lch  = tid & 7;
    const uint32_t ldst = lrow * 128 + ((lch * 16) ^ ((lrow & 7) << 4));
    const __half* aP = A + (size_t)(mt * BM + lrow) * K + lch * 8;
    const __half* bP[2];
    bP[0] = B0 + (size_t)(nt * BN_EACH + lrow) * K + lch * 8;
    bP[1] = B1 + (size_t)(nt * BN_EACH + lrow) * K + lch * 8;
    const size_t rstep = (size_t)32 * K;          // 32 rows forward

    // full-stage load (prologue only)
    auto load_stage = [&](int kc, int slot) {
        const uint32_t st = sb + slot * STAGE_BYTES + ldst;
        const int k0 = kc * BK;
#pragma unroll
        for (int it = 0; it < A_ITERS; it++)
            cp_async16(st + it * 4096, aP + k0 + it * rstep);
#pragma unroll
        for (int g = 0; g < NB; g++) {
            const __half* bp = bP[g] + k0;
            const uint32_t bbase = st + A_BYTES + g * B_BYTES;
#pragma unroll
            for (int it = 0; it < B_ITERS; it++)
                cp_async16(bbase + it * 4096, bp + it * rstep);
        }
    };

    // quarter-stage load: part p in 0..3 issues 1 A op + 1 B op
    auto load_part = [&](int kc, int slot, int p) {
        const uint32_t st = sb + slot * STAGE_BYTES + ldst;
        const int k0 = kc * BK;
        cp_async16(st + p * 4096, aP + k0 + p * rstep);
        if (NB == 2) {
            const int g  = p >> 1;
            const int it = p & 1;
            cp_async16(st + A_BYTES + g * B_BYTES + it * 4096,
                       bP[g] + k0 + it * rstep);
        } else {
            cp_async16(st + A_BYTES + p * 4096, bP[0] + k0 + p * rstep);
        }
    };

    // ---- prologue: stages 0..S-2, one commit group per stage ----
#pragma unroll
    for (int s = 0; s < STAGES - 1; s++) {
        load_stage(s, s);
        CP_COMMIT();
    }

    // ---- main loop: ONE sync per chunk; next-stage loads interleaved ----
    for (int kc = 0; kc < kch; kc++) {
        cp_wait<STAGES - 2>();           // stage kc resident
        __syncthreads();                 // + all warps done reading slot (kc-1)%S

        const int pre = kc + STAGES - 1;
        const bool do_pre = pre < kch;
        const int preslot = pre % STAGES;   // == (kc-1)%S, safe to overwrite

        const uint32_t st = sb + (kc % STAGES) * STAGE_BYTES;
#pragma unroll
        for (int ks = 0; ks < 4; ks++) {
            const uint32_t stk = st + kxo[ks];
            uint32_t fa[MI][4];
#pragma unroll
            for (int mi = 0; mi < MI; mi++)
                ldsm_x4(fa[mi][0], fa[mi][1], fa[mi][2], fa[mi][3],
                        stk + baseA[mi]);
            uint32_t fb[NJ][4];
#pragma unroll
            for (int jj = 0; jj < NJ; jj++)
                ldsm_x4(fb[jj][0], fb[jj][1], fb[jj][2], fb[jj][3],
                        stk + baseB[jj]);
            if (do_pre) load_part(pre, preslot, ks);   // 2 cp.asyncs amid MMAs
#pragma unroll
            for (int g = 0; g < NB; g++)
#pragma unroll
                for (int mi = 0; mi < MI; mi++)
#pragma unroll
                    for (int ni = 0; ni < NMMA; ni++)
                        mma16816(acc[g][mi][ni], fa[mi],
                                 &fb[g * (NMMA / 2) + (ni >> 1)][(ni & 1) * 2]);
        }
        CP_COMMIT();                     // one group per chunk (may be empty)
    }

    // ---- epilogue ----
    const float s0 = *s0p;
    const float s1 = *s1p;
    if (NB == 2) {
        __half* out = (__half*)outp;
#pragma unroll
        for (int mi = 0; mi < MI; mi++)
#pragma unroll
            for (int ni = 0; ni < NMMA; ni++) {
                int row0 = mt * BM + wm * 64 + mi * 16 + (lane >> 2);
                int col  = nt * BN_EACH + wn * WN_COLS + ni * 8 + (lane & 3) * 2;
#pragma unroll
                for (int h = 0; h < 2; h++) {
                    int row = row0 + h * 8;
                    float g0 = s0 * acc[0][mi][ni][2 * h + 0];
                    float g1 = s0 * acc[0][mi][ni][2 * h + 1];
                    float u0 = s1 * acc[1][mi][ni][2 * h + 0];
                    float u1 = s1 * acc[1][mi][ni][2 * h + 1];
                    float r0 = g0 / (1.f + __expf(-g0)) * u0;
                    float r1 = g1 / (1.f + __expf(-g1)) * u1;
                    *(__half2*)(out + (size_t)row * ncols + col) =
                        __floats2half2_rn(r0, r1);
                }
            }
    } else {
        float* out = (float*)outp;
#pragma unroll
        for (int mi = 0; mi < MI; mi++)
#pragma unroll
            for (int ni = 0; ni < NMMA; ni++) {
                int row0 = mt * BM + wm * 64 + mi * 16 + (lane >> 2);
                int col  = nt * BN_EACH + wn * WN_COLS + ni * 8 + (lane & 3) * 2;
#pragma unroll
                for (int h = 0; h < 2; h++) {
                    int row = row0 + h * 8;
                    float2 v;
                    v.x = s0 * acc[0][mi][ni][2 * h + 0];
                    v.y = s0 * acc[0][mi][ni][2 * h + 1];
                    *(float2*)(out + (size_t)row * ncols + col) = v;
                }
            }
    }
}

// ============================================================================
// Host side
// ============================================================================
extern "C" void kernel_launch(void* const* d_in, const int* in_sizes, int n_in,
                              void* d_out, int out_size) {
    const float* x  = (const float*)d_in[0];
    const int*   wg = (const int*)d_in[1];
    const int*   wu = (const int*)d_in[2];
    const int*   wd = (const int*)d_in[3];
    const float* sg = (const float*)d_in[4];
    const float* su = (const float*)d_in[5];
    const float* sd = (const float*)d_in[6];

    void *px, *pwg, *pwu, *pwd, *pmid;
    cudaGetSymbolAddress(&px,  g_x);
    cudaGetSymbolAddress(&pwg, g_wg);
    cudaGetSymbolAddress(&pwu, g_wu);
    cudaGetSymbolAddress(&pwd, g_wd);
    cudaGetSymbolAddress(&pmid, g_mid);

    constexpr int STAGES = 3;
    constexpr int SMEM_BYTES = STAGES * 32768;   // 98304 per CTA -> 2 CTAs/SM
    cudaFuncSetAttribute(ffn_gemm<2, 64, STAGES>,
                         cudaFuncAttributeMaxDynamicSharedMemorySize, SMEM_BYTES);
    cudaFuncSetAttribute(ffn_gemm<1, 128, STAGES>,
                         cudaFuncAttributeMaxDynamicSharedMemorySize, SMEM_BYTES);

    // Launch 1: all converts (one launch)
    cvt_all<<<BX + 3 * BW, 256>>>(
        (const float4*)x, (const int4*)wg, (const int4*)wu, (const int4*)wd,
        (uint4*)px, (uint4*)pwg, (uint4*)pwu, (uint4*)pwd);

    // Launch 2: GEMM1 fused gate+up+SwiGLU -> g_mid (fp16). Tile 128 x 64x2.
    {
        int mtiles = MROWS / 128;   // 64
        int ntiles = HID / 64;      // 172
        ffn_gemm<2, 64, STAGES><<<mtiles * ntiles, 256, SMEM_BYTES>>>(
            (const __half*)px, (const __half*)pwg, (const __half*)pwu,
            pmid, sg, su, DIMN, ntiles, HID);
    }

    // Launch 3: GEMM2 down projection -> d_out (fp32). Tile 128 x 128.
    {
        int mtiles = MROWS / 128;   // 64
        int ntiles = DIMN / 128;    // 32
        ffn_gemm<1, 128, STAGES><<<mtiles * ntiles, 256, SMEM_BYTES>>>(
            (const __half*)pmid, (const __half*)pwd, (const __half*)pwd,
            d_out, sd, sd, HID, ntiles, DIMN);
    }
}

// round 12
// speedup vs baseline: 1.2462x; 1.0121x over previous
#include <cuda_runtime.h>
#include <cuda_fp16.h>
#include <cstdint>

// ============================================================================
// Problem sizes (fixed for this dataset)
// ============================================================================
static constexpr int DIMN  = 4096;
static constexpr int HID   = 11008;
static constexpr int MROWS = 8192;   // B*S = 4*2048

// ============================================================================
// Device scratch (allocation-free rule: __device__ globals)
// ============================================================================
static __device__ __align__(256) __half g_x  [(size_t)MROWS * DIMN];
static __device__ __align__(256) __half g_wg [(size_t)HID   * DIMN];
static __device__ __align__(256) __half g_wu [(size_t)HID   * DIMN];
static __device__ __align__(256) __half g_wd [(size_t)DIMN  * HID ];
static __device__ __align__(256) __half g_mid[(size_t)MROWS * HID ];

// ============================================================================
// PTX helpers — compute_103-safe only (cp.async, ldmatrix, mma.sync.m16n8k16)
// ============================================================================
__device__ __forceinline__ uint32_t smem_to_u32(const void* smem_ptr) {
    uint32_t addr;
    asm("{ .reg .u64 tmp; cvta.to.shared.u64 tmp, %1; cvt.u32.u64 %0, tmp; }"
        : "=r"(addr) : "l"(smem_ptr));
    return addr;
}

__device__ __forceinline__ void cp_async16(uint32_t dst, const void* src) {
    asm volatile("cp.async.cg.shared.global [%0], [%1], 16;\n"
                 :: "r"(dst), "l"(src) : "memory");
}
#define CP_COMMIT() asm volatile("cp.async.commit_group;\n" ::: "memory")
template <int N>
__device__ __forceinline__ void cp_wait() {
    asm volatile("cp.async.wait_group %0;\n" :: "n"(N) : "memory");
}

__device__ __forceinline__ void ldsm_x4(uint32_t& r0, uint32_t& r1,
                                        uint32_t& r2, uint32_t& r3, uint32_t addr) {
    asm volatile("ldmatrix.sync.aligned.m8n8.x4.shared.b16 {%0,%1,%2,%3}, [%4];"
                 : "=r"(r0), "=r"(r1), "=r"(r2), "=r"(r3) : "r"(addr));
}

__device__ __forceinline__ void mma16816(float* c, const uint32_t* a, const uint32_t* b) {
    asm volatile(
        "mma.sync.aligned.m16n8k16.row.col.f32.f16.f16.f32 "
        "{%0,%1,%2,%3}, {%4,%5,%6,%7}, {%8,%9}, {%0,%1,%2,%3};"
        : "+f"(c[0]), "+f"(c[1]), "+f"(c[2]), "+f"(c[3])
        : "r"(a[0]), "r"(a[1]), "r"(a[2]), "r"(a[3]), "r"(b[0]), "r"(b[1]));
}

// ============================================================================
// Merged dequant/convert (one launch; DRAM-bound, ~138us)
// ============================================================================
static constexpr int N8X = (MROWS * DIMN) / 8;   // 4,194,304 -> 16384 blocks
static constexpr int N8W = (HID * DIMN) / 8;     // 5,636,096 -> 22016 blocks
static constexpr int BX  = N8X / 256;            // 16384
static constexpr int BW  = N8W / 256;            // 22016

__global__ void __launch_bounds__(256) cvt_all(
    const float4* __restrict__ x, const int4* __restrict__ wg,
    const int4* __restrict__ wu, const int4* __restrict__ wd,
    uint4* __restrict__ ox, uint4* __restrict__ owg,
    uint4* __restrict__ owu, uint4* __restrict__ owd)
{
    int b = blockIdx.x;
    if (b < BX) {
        int i = b * 256 + threadIdx.x;
        float4 a = x[2 * i];
        float4 c = x[2 * i + 1];
        __half2 h0 = __floats2half2_rn(a.x, a.y);
        __half2 h1 = __floats2half2_rn(a.z, a.w);
        __half2 h2 = __floats2half2_rn(c.x, c.y);
        __half2 h3 = __floats2half2_rn(c.z, c.w);
        uint4 r;
        r.x = *reinterpret_cast<uint32_t*>(&h0);
        r.y = *reinterpret_cast<uint32_t*>(&h1);
        r.z = *reinterpret_cast<uint32_t*>(&h2);
        r.w = *reinterpret_cast<uint32_t*>(&h3);
        ox[i] = r;
        return;
    }
    b -= BX;
    const int4* src;
    uint4* dst;
    if (b < BW)            { src = wg; dst = owg; }
    else if (b < 2 * BW)   { src = wu; dst = owu; b -= BW; }
    else                   { src = wd; dst = owd; b -= 2 * BW; }
    int i = b * 256 + threadIdx.x;
    int4 a = src[2 * i];
    int4 c = src[2 * i + 1];
    __half2 h0 = __halves2half2(__int2half_rn(a.x), __int2half_rn(a.y));
    __half2 h1 = __halves2half2(__int2half_rn(a.z), __int2half_rn(a.w));
    __half2 h2 = __halves2half2(__int2half_rn(c.x), __int2half_rn(c.y));
    __half2 h3 = __halves2half2(__int2half_rn(c.z), __int2half_rn(c.w));
    uint4 r;
    r.x = *reinterpret_cast<uint32_t*>(&h0);
    r.y = *reinterpret_cast<uint32_t*>(&h1);
    r.z = *reinterpret_cast<uint32_t*>(&h2);
    r.w = *reinterpret_cast<uint32_t*>(&h3);
    dst[i] = r;
}

// ============================================================================
// PERSISTENT multistage cp.async + mma.sync GEMM (C = A * B^T).
//   NB==2 (BN_EACH=64):  gate+up share A tile; fused SwiGLU -> fp16 mid.
//   NB==1 (BN_EACH=128): down proj; scaled fp32 out.
// CTA tile 128 x 128-total x 64k; 8 warps 2m x 4n; occupancy 2 (3 stages x
// 32KB smem). Each CTA walks tiles t, t+G, ... with a NEVER-DRAINING
// pipeline: during the last 2 chunks of a tile the interleaved prefetch
// switches to chunks 0,1 of the next tile, so the epilogue overlaps the
// next tile's prologue loads. Slot/commit/wait invariants identical to the
// proven non-persistent schedule (one commit group per chunk, wait<1>).
// ============================================================================
template <int NB, int BN_EACH>
__global__ void __launch_bounds__(256, 2) ffn_gemm(
    const __half* __restrict__ A,
    const __half* __restrict__ B0,
    const __half* __restrict__ B1,
    void* __restrict__ outp,
    const float* __restrict__ s0p,
    const float* __restrict__ s1p,
    int K, int ntiles, int ntotal, int ncols)
{
    constexpr int BM = 128, BK = 64;
    constexpr int NTHR = 256;
    constexpr int STAGES = 3;
    constexpr int WN_COLS = BN_EACH / 4;
    constexpr int MI   = 4;
    constexpr int NMMA = WN_COLS / 8;
    constexpr int NJ   = NB * (NMMA / 2);
    constexpr int A_BYTES = BM * BK * 2;
    constexpr int B_BYTES = BN_EACH * BK * 2;
    constexpr int STAGE_BYTES = A_BYTES + NB * B_BYTES;   // 32768
    constexpr int A_ITERS = (BM * 8) / NTHR;
    constexpr int B_ITERS = (BN_EACH * 8) / NTHR;
    constexpr int GM = 8;

    extern __shared__ char smem[];
    const uint32_t sb = smem_to_u32(smem);

    const int tid  = threadIdx.x;
    const int wid  = tid >> 5;
    const int lane = tid & 31;
    const int wm   = wid & 1;
    const int wn   = wid >> 1;
    const int quad = lane >> 3;
    const int qr   = lane & 7;

    const int kch = K / BK;
    const int G   = gridDim.x;

    // ---- hoisted LDSM address components (row&7 == qr for all fragments) ---
    const uint32_t xr   = (uint32_t)(qr << 4);
    const uint32_t xr60 = xr & 0x60;
    const uint32_t xr10 = xr & 0x10;
    uint32_t kxo[4];
#pragma unroll
    for (int ks = 0; ks < 4; ks++) kxo[ks] = ((uint32_t)(ks * 32)) ^ xr60;

    uint32_t baseA[MI];
#pragma unroll
    for (int mi = 0; mi < MI; mi++) {
        int row = wm * 64 + mi * 16 + (quad & 1) * 8 + qr;
        baseA[mi] = (uint32_t)(row * 128) + (((uint32_t)((quad >> 1) * 16)) ^ xr10);
    }
    uint32_t baseB[NJ];
#pragma unroll
    for (int g = 0; g < NB; g++)
#pragma unroll
        for (int j = 0; j < NMMA / 2; j++) {
            int row = wn * WN_COLS + j * 16 + (quad >> 1) * 8 + qr;
            baseB[g * (NMMA / 2) + j] =
                (uint32_t)(A_BYTES + g * B_BYTES + row * 128) +
                (((uint32_t)((quad & 1) * 16)) ^ xr10);
        }

    // ---- loader thread constants ----
    const int lrow = tid >> 3;                    // 0..31
    const int lch  = tid & 7;
    const uint32_t ldst = lrow * 128 + ((lch * 16) ^ ((lrow & 7) << 4));
    const size_t rstep = (size_t)32 * K;

    // tile decode (GM-swizzled, same mapping as non-persistent version)
    auto decode = [&](int t, int& mt, int& nt) {
        const int tpg = GM * ntiles;
        mt = (t / tpg) * GM + (t % tpg) % GM;
        nt = (t % tpg) / GM;
    };

    // prefetch-tile pointers (updated at tile switch)
    const __half* aP;
    const __half* bP0;
    const __half* bP1;
    auto set_ptrs = [&](int t) {
        int mt, nt;
        decode(t, mt, nt);
        aP  = A  + (size_t)(mt * BM + lrow) * K + lch * 8;
        bP0 = B0 + (size_t)(nt * BN_EACH + lrow) * K + lch * 8;
        bP1 = B1 + (size_t)(nt * BN_EACH + lrow) * K + lch * 8;
    };

    // full-stage load (prologue of very first tile only)
    auto load_stage = [&](int kc, int slot) {
        const uint32_t st = sb + slot * STAGE_BYTES + ldst;
        const int k0 = kc * BK;
#pragma unroll
        for (int it = 0; it < A_ITERS; it++)
            cp_async16(st + it * 4096, aP + k0 + it * rstep);
        const uint32_t bbase = st + A_BYTES;
#pragma unroll
        for (int it = 0; it < B_ITERS; it++)
            cp_async16(bbase + it * 4096, bP0 + k0 + it * rstep);
        if (NB == 2) {
#pragma unroll
            for (int it = 0; it < B_ITERS; it++)
                cp_async16(bbase + B_BYTES + it * 4096, bP1 + k0 + it * rstep);
        }
    };

    // quarter-stage load: part p in 0..3 issues 1 A op + 1 B op
    auto load_part = [&](int kc, int slot, int p) {
        const uint32_t st = sb + slot * STAGE_BYTES + ldst;
        const int k0 = kc * BK;
        cp_async16(st + p * 4096, aP + k0 + p * rstep);
        if (NB == 2) {
            const __half* bp = (p >> 1) ? bP1 : bP0;
            const int it = p & 1;
            cp_async16(st + A_BYTES + (p >> 1) * B_BYTES + it * 4096,
                       bp + k0 + it * rstep);
        } else {
            cp_async16(st + A_BYTES + p * 4096, bP0 + k0 + p * rstep);
        }
    };

    float acc[NB][MI][NMMA][4];
#pragma unroll
    for (int g = 0; g < NB; g++)
#pragma unroll
        for (int mi = 0; mi < MI; mi++)
#pragma unroll
            for (int ni = 0; ni < NMMA; ni++)
#pragma unroll
                for (int q = 0; q < 4; q++) acc[g][mi][ni][q] = 0.f;

    int t = blockIdx.x;
    if (t >= ntotal) return;
    set_ptrs(t);

    // prologue: chunks 0,1 of first tile -> slots 0,1
    load_stage(0, 0); CP_COMMIT();
    load_stage(1, 1); CP_COMMIT();
    int cslot = 0;                       // slot of the chunk being computed

    const float s0 = *s0p;
    const float s1 = *s1p;

    for (; t < ntotal; t += G) {
        const bool has_next = (t + G) < ntotal;

        for (int kc = 0; kc < kch; kc++) {
            cp_wait<1>();
            __syncthreads();

            // prefetch-stream tile switch: chunks kch-2, kch-1 prefetch
            // chunks 0, 1 of the next tile
            if (kc == kch - 2 && has_next) set_ptrs(t + G);
            const bool do_pre = (kc < kch - 2) || has_next;
            const int preK = (kc + 2 < kch) ? (kc + 2) : (kc + 2 - kch);
            const int pslot = (cslot + 2 >= 3) ? (cslot - 1) : (cslot + 2);

            const uint32_t st = sb + cslot * STAGE_BYTES;
#pragma unroll
            for (int ks = 0; ks < 4; ks++) {
                const uint32_t stk = st + kxo[ks];
                uint32_t fa[MI][4];
#pragma unroll
                for (int mi = 0; mi < MI; mi++)
                    ldsm_x4(fa[mi][0], fa[mi][1], fa[mi][2], fa[mi][3],
                            stk + baseA[mi]);
                uint32_t fb[NJ][4];
#pragma unroll
                for (int jj = 0; jj < NJ; jj++)
                    ldsm_x4(fb[jj][0], fb[jj][1], fb[jj][2], fb[jj][3],
                            stk + baseB[jj]);
                if (do_pre) load_part(preK, pslot, ks);
#pragma unroll
                for (int g = 0; g < NB; g++)
#pragma unroll
                    for (int mi = 0; mi < MI; mi++)
#pragma unroll
                        for (int ni = 0; ni < NMMA; ni++)
                            mma16816(acc[g][mi][ni], fa[mi],
                                     &fb[g * (NMMA / 2) + (ni >> 1)][(ni & 1) * 2]);
            }
            CP_COMMIT();                 // one group per chunk (may be empty)
            cslot = (cslot + 1 == 3) ? 0 : cslot + 1;
        }

        // ---- epilogue for tile t (overlaps next tile's in-flight loads) ----
        int mt, nt;
        decode(t, mt, nt);
        if (NB == 2) {
            __half* out = (__half*)outp;
#pragma unroll
            for (int mi = 0; mi < MI; mi++)
#pragma unroll
                for (int ni = 0; ni < NMMA; ni++) {
                    int row0 = mt * BM + wm * 64 + mi * 16 + (lane >> 2);
                    int col  = nt * BN_EACH + wn * WN_COLS + ni * 8 + (lane & 3) * 2;
#pragma unroll
                    for (int h = 0; h < 2; h++) {
                        int row = row0 + h * 8;
                        float g0 = s0 * acc[0][mi][ni][2 * h + 0];
                        float g1 = s0 * acc[0][mi][ni][2 * h + 1];
                        float u0 = s1 * acc[1][mi][ni][2 * h + 0];
                        float u1 = s1 * acc[1][mi][ni][2 * h + 1];
                        float r0 = g0 / (1.f + __expf(-g0)) * u0;
                        float r1 = g1 / (1.f + __expf(-g1)) * u1;
                        *(__half2*)(out + (size_t)row * ncols + col) =
                            __floats2half2_rn(r0, r1);
                    }
                }
        } else {
            float* out = (float*)outp;
#pragma unroll
            for (int mi = 0; mi < MI; mi++)
#pragma unroll
                for (int ni = 0; ni < NMMA; ni++) {
                    int row0 = mt * BM + wm * 64 + mi * 16 + (lane >> 2);
                    int col  = nt * BN_EACH + wn * WN_COLS + ni * 8 + (lane & 3) * 2;
#pragma unroll
                    for (int h = 0; h < 2; h++) {
                        int row = row0 + h * 8;
                        float2 v;
                        v.x = s0 * acc[0][mi][ni][2 * h + 0];
                        v.y = s0 * acc[0][mi][ni][2 * h + 1];
                        *(float2*)(out + (size_t)row * ncols + col) = v;
                    }
                }
        }
        // reset accumulators for the next tile
#pragma unroll
        for (int g = 0; g < NB; g++)
#pragma unroll
            for (int mi = 0; mi < MI; mi++)
#pragma unroll
                for (int ni = 0; ni < NMMA; ni++)
#pragma unroll
                    for (int q = 0; q < 4; q++) acc[g][mi][ni][q] = 0.f;
    }
}

// ============================================================================
// Host side
// ============================================================================
extern "C" void kernel_launch(void* const* d_in, const int* in_sizes, int n_in,
                              void* d_out, int out_size) {
    const float* x  = (const float*)d_in[0];
    const int*   wg = (const int*)d_in[1];
    const int*   wu = (const int*)d_in[2];
    const int*   wd = (const int*)d_in[3];
    const float* sg = (const float*)d_in[4];
    const float* su = (const float*)d_in[5];
    const float* sd = (const float*)d_in[6];

    void *px, *pwg, *pwu, *pwd, *pmid;
    cudaGetSymbolAddress(&px,  g_x);
    cudaGetSymbolAddress(&pwg, g_wg);
    cudaGetSymbolAddress(&pwu, g_wu);
    cudaGetSymbolAddress(&pwd, g_wd);
    cudaGetSymbolAddress(&pmid, g_mid);

    int dev = 0, sms = 148;
    cudaGetDevice(&dev);
    cudaDeviceGetAttribute(&sms, cudaDevAttrMultiProcessorCount, dev);
    const int gpersist = 2 * sms;

    constexpr int SMEM_BYTES = 3 * 32768;   // 98304 per CTA -> 2 CTAs/SM
    cudaFuncSetAttribute(ffn_gemm<2, 64>,
                         cudaFuncAttributeMaxDynamicSharedMemorySize, SMEM_BYTES);
    cudaFuncSetAttribute(ffn_gemm<1, 128>,
                         cudaFuncAttributeMaxDynamicSharedMemorySize, SMEM_BYTES);

    // Launch 1: all converts (one launch)
    cvt_all<<<BX + 3 * BW, 256>>>(
        (const float4*)x, (const int4*)wg, (const int4*)wu, (const int4*)wd,
        (uint4*)px, (uint4*)pwg, (uint4*)pwu, (uint4*)pwd);

    // Launch 2: GEMM1 fused gate+up+SwiGLU -> g_mid (fp16). Persistent.
    {
        int mtiles = MROWS / 128;   // 64
        int ntiles = HID / 64;      // 172
        int ntotal = mtiles * ntiles;
        int grid = gpersist < ntotal ? gpersist : ntotal;
        ffn_gemm<2, 64><<<grid, 256, SMEM_BYTES>>>(
            (const __half*)px, (const __half*)pwg, (const __half*)pwu,
            pmid, sg, su, DIMN, ntiles, ntotal, HID);
    }

    // Launch 3: GEMM2 down projection -> d_out (fp32). Persistent.
    {
        int mtiles = MROWS / 128;   // 64
        int ntiles = DIMN / 128;    // 32
        int ntotal = mtiles * ntiles;
        int grid = gpersist < ntotal ? gpersist : ntotal;
        ffn_gemm<1, 128><<<grid, 256, SMEM_BYTES>>>(
            (const __half*)pmid, (const __half*)pwd, (const __half*)pwd,
            d_out, sd, sd, HID, ntiles, ntotal, DIMN);
    }
}

// round 13
// speedup vs baseline: 1.2473x; 1.0009x over previous
#include <cuda_runtime.h>
#include <cuda_fp16.h>
#include <cstdint>

// ============================================================================
// Problem sizes (fixed for this dataset)
// ============================================================================
static constexpr int DIMN  = 4096;
static constexpr int HID   = 11008;
static constexpr int MROWS = 8192;   // B*S = 4*2048

// ============================================================================
// Device scratch (allocation-free rule: __device__ globals)
// ============================================================================
static __device__ __align__(256) __half g_x  [(size_t)MROWS * DIMN];
static __device__ __align__(256) __half g_wg [(size_t)HID   * DIMN];
static __device__ __align__(256) __half g_wu [(size_t)HID   * DIMN];
static __device__ __align__(256) __half g_wd [(size_t)DIMN  * HID ];
static __device__ __align__(256) __half g_mid[(size_t)MROWS * HID ];

// ============================================================================
// PTX helpers — compute_103-safe only (cp.async, ldmatrix, mma.sync.m16n8k16)
// ============================================================================
__device__ __forceinline__ uint32_t smem_to_u32(const void* smem_ptr) {
    uint32_t addr;
    asm("{ .reg .u64 tmp; cvta.to.shared.u64 tmp, %1; cvt.u32.u64 %0, tmp; }"
        : "=r"(addr) : "l"(smem_ptr));
    return addr;
}

__device__ __forceinline__ void cp_async16(uint32_t dst, const void* src) {
    asm volatile("cp.async.cg.shared.global [%0], [%1], 16;\n"
                 :: "r"(dst), "l"(src) : "memory");
}
#define CP_COMMIT() asm volatile("cp.async.commit_group;\n" ::: "memory")
template <int N>
__device__ __forceinline__ void cp_wait() {
    asm volatile("cp.async.wait_group %0;\n" :: "n"(N) : "memory");
}

__device__ __forceinline__ void ldsm_x4(uint32_t& r0, uint32_t& r1,
                                        uint32_t& r2, uint32_t& r3, uint32_t addr) {
    asm volatile("ldmatrix.sync.aligned.m8n8.x4.shared.b16 {%0,%1,%2,%3}, [%4];"
                 : "=r"(r0), "=r"(r1), "=r"(r2), "=r"(r3) : "r"(addr));
}

__device__ __forceinline__ void mma16816(float* c, const uint32_t* a, const uint32_t* b) {
    asm volatile(
        "mma.sync.aligned.m16n8k16.row.col.f32.f16.f16.f32 "
        "{%0,%1,%2,%3}, {%4,%5,%6,%7}, {%8,%9}, {%0,%1,%2,%3};"
        : "+f"(c[0]), "+f"(c[1]), "+f"(c[2]), "+f"(c[3])
        : "r"(a[0]), "r"(a[1]), "r"(a[2]), "r"(a[3]), "r"(b[0]), "r"(b[1]));
}

// ============================================================================
// Converts, split: cvt_xw (x + gate/up, blocks GEMM1) and cvt_wd (down-proj,
// runs on a forked stream overlapped with GEMM1).
// ============================================================================
static constexpr int N8X = (MROWS * DIMN) / 8;   // 4,194,304 -> 16384 blocks
static constexpr int N8W = (HID * DIMN) / 8;     // 5,636,096 -> 22016 blocks
static constexpr int BX  = N8X / 256;            // 16384
static constexpr int BW  = N8W / 256;            // 22016

__device__ __forceinline__ uint4 cvt_i32x8(const int4* src, int i) {
    int4 a = src[2 * i];
    int4 c = src[2 * i + 1];
    __half2 h0 = __halves2half2(__int2half_rn(a.x), __int2half_rn(a.y));
    __half2 h1 = __halves2half2(__int2half_rn(a.z), __int2half_rn(a.w));
    __half2 h2 = __halves2half2(__int2half_rn(c.x), __int2half_rn(c.y));
    __half2 h3 = __halves2half2(__int2half_rn(c.z), __int2half_rn(c.w));
    uint4 r;
    r.x = *reinterpret_cast<uint32_t*>(&h0);
    r.y = *reinterpret_cast<uint32_t*>(&h1);
    r.z = *reinterpret_cast<uint32_t*>(&h2);
    r.w = *reinterpret_cast<uint32_t*>(&h3);
    return r;
}

__global__ void __launch_bounds__(256) cvt_xw(
    const float4* __restrict__ x, const int4* __restrict__ wg,
    const int4* __restrict__ wu,
    uint4* __restrict__ ox, uint4* __restrict__ owg, uint4* __restrict__ owu)
{
    int b = blockIdx.x;
    if (b < BX) {
        int i = b * 256 + threadIdx.x;
        float4 a = x[2 * i];
        float4 c = x[2 * i + 1];
        __half2 h0 = __floats2half2_rn(a.x, a.y);
        __half2 h1 = __floats2half2_rn(a.z, a.w);
        __half2 h2 = __floats2half2_rn(c.x, c.y);
        __half2 h3 = __floats2half2_rn(c.z, c.w);
        uint4 r;
        r.x = *reinterpret_cast<uint32_t*>(&h0);
        r.y = *reinterpret_cast<uint32_t*>(&h1);
        r.z = *reinterpret_cast<uint32_t*>(&h2);
        r.w = *reinterpret_cast<uint32_t*>(&h3);
        ox[i] = r;
        return;
    }
    b -= BX;
    if (b < BW) { owg[b * 256 + threadIdx.x] = cvt_i32x8(wg, b * 256 + threadIdx.x); }
    else        { b -= BW; owu[b * 256 + threadIdx.x] = cvt_i32x8(wu, b * 256 + threadIdx.x); }
}

__global__ void __launch_bounds__(256) cvt_wd(const int4* __restrict__ wd,
                                              uint4* __restrict__ owd)
{
    int i = blockIdx.x * 256 + threadIdx.x;
    owd[i] = cvt_i32x8(wd, i);
}

// ============================================================================
// PERSISTENT multistage cp.async + mma.sync GEMM (C = A * B^T).
//   NB==2 (BN_EACH=64):  gate+up share A tile; fused SwiGLU -> fp16 mid.
//   NB==1 (BN_EACH=128): down proj; scaled fp32 out.
// CTA tile 128 x 128-total x 64k; 8 warps 2m x 4n; occupancy 2 (3 stages x
// 32KB smem). Never-draining pipeline across tiles (epilogue overlaps next
// tile's prologue loads). Identical to the R12 champion.
// ============================================================================
template <int NB, int BN_EACH>
__global__ void __launch_bounds__(256, 2) ffn_gemm(
    const __half* __restrict__ A,
    const __half* __restrict__ B0,
    const __half* __restrict__ B1,
    void* __restrict__ outp,
    const float* __restrict__ s0p,
    const float* __restrict__ s1p,
    int K, int ntiles, int ntotal, int ncols)
{
    constexpr int BM = 128, BK = 64;
    constexpr int NTHR = 256;
    constexpr int WN_COLS = BN_EACH / 4;
    constexpr int MI   = 4;
    constexpr int NMMA = WN_COLS / 8;
    constexpr int NJ   = NB * (NMMA / 2);
    constexpr int A_BYTES = BM * BK * 2;
    constexpr int B_BYTES = BN_EACH * BK * 2;
    constexpr int STAGE_BYTES = A_BYTES + NB * B_BYTES;   // 32768
    constexpr int A_ITERS = (BM * 8) / NTHR;
    constexpr int B_ITERS = (BN_EACH * 8) / NTHR;
    constexpr int GM = 8;

    extern __shared__ char smem[];
    const uint32_t sb = smem_to_u32(smem);

    const int tid  = threadIdx.x;
    const int wid  = tid >> 5;
    const int lane = tid & 31;
    const int wm   = wid & 1;
    const int wn   = wid >> 1;
    const int quad = lane >> 3;
    const int qr   = lane & 7;

    const int kch = K / BK;
    const int G   = gridDim.x;

    // ---- hoisted LDSM address components (row&7 == qr for all fragments) ---
    const uint32_t xr   = (uint32_t)(qr << 4);
    const uint32_t xr60 = xr & 0x60;
    const uint32_t xr10 = xr & 0x10;
    uint32_t kxo[4];
#pragma unroll
    for (int ks = 0; ks < 4; ks++) kxo[ks] = ((uint32_t)(ks * 32)) ^ xr60;

    uint32_t baseA[MI];
#pragma unroll
    for (int mi = 0; mi < MI; mi++) {
        int row = wm * 64 + mi * 16 + (quad & 1) * 8 + qr;
        baseA[mi] = (uint32_t)(row * 128) + (((uint32_t)((quad >> 1) * 16)) ^ xr10);
    }
    uint32_t baseB[NJ];
#pragma unroll
    for (int g = 0; g < NB; g++)
#pragma unroll
        for (int j = 0; j < NMMA / 2; j++) {
            int row = wn * WN_COLS + j * 16 + (quad >> 1) * 8 + qr;
            baseB[g * (NMMA / 2) + j] =
                (uint32_t)(A_BYTES + g * B_BYTES + row * 128) +
                (((uint32_t)((quad & 1) * 16)) ^ xr10);
        }

    // ---- loader thread constants ----
    const int lrow = tid >> 3;                    // 0..31
    const int lch  = tid & 7;
    const uint32_t ldst = lrow * 128 + ((lch * 16) ^ ((lrow & 7) << 4));
    const size_t rstep = (size_t)32 * K;

    auto decode = [&](int t, int& mt, int& nt) {
        const int tpg = GM * ntiles;
        mt = (t / tpg) * GM + (t % tpg) % GM;
        nt = (t % tpg) / GM;
    };

    const __half* aP;
    const __half* bP0;
    const __half* bP1;
    auto set_ptrs = [&](int t) {
        int mt, nt;
        decode(t, mt, nt);
        aP  = A  + (size_t)(mt * BM + lrow) * K + lch * 8;
        bP0 = B0 + (size_t)(nt * BN_EACH + lrow) * K + lch * 8;
        bP1 = B1 + (size_t)(nt * BN_EACH + lrow) * K + lch * 8;
    };

    auto load_stage = [&](int kc, int slot) {
        const uint32_t st = sb + slot * STAGE_BYTES + ldst;
        const int k0 = kc * BK;
#pragma unroll
        for (int it = 0; it < A_ITERS; it++)
            cp_async16(st + it * 4096, aP + k0 + it * rstep);
        const uint32_t bbase = st + A_BYTES;
#pragma unroll
        for (int it = 0; it < B_ITERS; it++)
            cp_async16(bbase + it * 4096, bP0 + k0 + it * rstep);
        if (NB == 2) {
#pragma unroll
            for (int it = 0; it < B_ITERS; it++)
                cp_async16(bbase + B_BYTES + it * 4096, bP1 + k0 + it * rstep);
        }
    };

    auto load_part = [&](int kc, int slot, int p) {
        const uint32_t st = sb + slot * STAGE_BYTES + ldst;
        const int k0 = kc * BK;
        cp_async16(st + p * 4096, aP + k0 + p * rstep);
        if (NB == 2) {
            const __half* bp = (p >> 1) ? bP1 : bP0;
            const int it = p & 1;
            cp_async16(st + A_BYTES + (p >> 1) * B_BYTES + it * 4096,
                       bp + k0 + it * rstep);
        } else {
            cp_async16(st + A_BYTES + p * 4096, bP0 + k0 + p * rstep);
        }
    };

    float acc[NB][MI][NMMA][4];
#pragma unroll
    for (int g = 0; g < NB; g++)
#pragma unroll
        for (int mi = 0; mi < MI; mi++)
#pragma unroll
            for (int ni = 0; ni < NMMA; ni++)
#pragma unroll
                for (int q = 0; q < 4; q++) acc[g][mi][ni][q] = 0.f;

    int t = blockIdx.x;
    if (t >= ntotal) return;
    set_ptrs(t);

    load_stage(0, 0); CP_COMMIT();
    load_stage(1, 1); CP_COMMIT();
    int cslot = 0;

    const float s0 = *s0p;
    const float s1 = *s1p;

    for (; t < ntotal; t += G) {
        const bool has_next = (t + G) < ntotal;

        for (int kc = 0; kc < kch; kc++) {
            cp_wait<1>();
            __syncthreads();

            if (kc == kch - 2 && has_next) set_ptrs(t + G);
            const bool do_pre = (kc < kch - 2) || has_next;
            const int preK = (kc + 2 < kch) ? (kc + 2) : (kc + 2 - kch);
            const int pslot = (cslot + 2 >= 3) ? (cslot - 1) : (cslot + 2);

            const uint32_t st = sb + cslot * STAGE_BYTES;
#pragma unroll
            for (int ks = 0; ks < 4; ks++) {
                const uint32_t stk = st + kxo[ks];
                uint32_t fa[MI][4];
#pragma unroll
                for (int mi = 0; mi < MI; mi++)
                    ldsm_x4(fa[mi][0], fa[mi][1], fa[mi][2], fa[mi][3],
                            stk + baseA[mi]);
                uint32_t fb[NJ][4];
#pragma unroll
                for (int jj = 0; jj < NJ; jj++)
                    ldsm_x4(fb[jj][0], fb[jj][1], fb[jj][2], fb[jj][3],
                            stk + baseB[jj]);
                if (do_pre) load_part(preK, pslot, ks);
#pragma unroll
                for (int g = 0; g < NB; g++)
#pragma unroll
                    for (int mi = 0; mi < MI; mi++)
#pragma unroll
                        for (int ni = 0; ni < NMMA; ni++)
                            mma16816(acc[g][mi][ni], fa[mi],
                                     &fb[g * (NMMA / 2) + (ni >> 1)][(ni & 1) * 2]);
            }
            CP_COMMIT();
            cslot = (cslot + 1 == 3) ? 0 : cslot + 1;
        }

        int mt, nt;
        decode(t, mt, nt);
        if (NB == 2) {
            __half* out = (__half*)outp;
#pragma unroll
            for (int mi = 0; mi < MI; mi++)
#pragma unroll
                for (int ni = 0; ni < NMMA; ni++) {
                    int row0 = mt * BM + wm * 64 + mi * 16 + (lane >> 2);
                    int col  = nt * BN_EACH + wn * WN_COLS + ni * 8 + (lane & 3) * 2;
#pragma unroll
                    for (int h = 0; h < 2; h++) {
                        int row = row0 + h * 8;
                        float g0 = s0 * acc[0][mi][ni][2 * h + 0];
                        float g1 = s0 * acc[0][mi][ni][2 * h + 1];
                        float u0 = s1 * acc[1][mi][ni][2 * h + 0];
                        float u1 = s1 * acc[1][mi][ni][2 * h + 1];
                        float r0 = g0 / (1.f + __expf(-g0)) * u0;
                        float r1 = g1 / (1.f + __expf(-g1)) * u1;
                        *(__half2*)(out + (size_t)row * ncols + col) =
                            __floats2half2_rn(r0, r1);
                    }
                }
        } else {
            float* out = (float*)outp;
#pragma unroll
            for (int mi = 0; mi < MI; mi++)
#pragma unroll
                for (int ni = 0; ni < NMMA; ni++) {
                    int row0 = mt * BM + wm * 64 + mi * 16 + (lane >> 2);
                    int col  = nt * BN_EACH + wn * WN_COLS + ni * 8 + (lane & 3) * 2;
#pragma unroll
                    for (int h = 0; h < 2; h++) {
                        int row = row0 + h * 8;
                        float2 v;
                        v.x = s0 * acc[0][mi][ni][2 * h + 0];
                        v.y = s0 * acc[0][mi][ni][2 * h + 1];
                        *(float2*)(out + (size_t)row * ncols + col) = v;
                    }
                }
        }
#pragma unroll
        for (int g = 0; g < NB; g++)
#pragma unroll
            for (int mi = 0; mi < MI; mi++)
#pragma unroll
                for (int ni = 0; ni < NMMA; ni++)
#pragma unroll
                    for (int q = 0; q < 4; q++) acc[g][mi][ni][q] = 0.f;
    }
}

// ============================================================================
// Host side — fork-join stream overlap: cvt_wd runs concurrently with GEMM1.
//   main:  cvt_xw -> GEMM1 ----------------+-> GEMM2
//   fork:        \-> cvt_wd (event join) --/
// Stream/events created per call (host-side only; kernel_launch is invoked
// O(1) times: correctness + capture).
// ============================================================================
extern "C" void kernel_launch(void* const* d_in, const int* in_sizes, int n_in,
                              void* d_out, int out_size) {
    const float* x  = (const float*)d_in[0];
    const int*   wg = (const int*)d_in[1];
    const int*   wu = (const int*)d_in[2];
    const int*   wd = (const int*)d_in[3];
    const float* sg = (const float*)d_in[4];
    const float* su = (const float*)d_in[5];
    const float* sd = (const float*)d_in[6];

    void *px, *pwg, *pwu, *pwd, *pmid;
    cudaGetSymbolAddress(&px,  g_x);
    cudaGetSymbolAddress(&pwg, g_wg);
    cudaGetSymbolAddress(&pwu, g_wu);
    cudaGetSymbolAddress(&pwd, g_wd);
    cudaGetSymbolAddress(&pmid, g_mid);

    int dev = 0, sms = 148;
    cudaGetDevice(&dev);
    cudaDeviceGetAttribute(&sms, cudaDevAttrMultiProcessorCount, dev);
    const int gpersist = 2 * sms;

    constexpr int SMEM_BYTES = 3 * 32768;   // 98304 per CTA -> 2 CTAs/SM
    cudaFuncSetAttribute(ffn_gemm<2, 64>,
                         cudaFuncAttributeMaxDynamicSharedMemorySize, SMEM_BYTES);
    cudaFuncSetAttribute(ffn_gemm<1, 128>,
                         cudaFuncAttributeMaxDynamicSharedMemorySize, SMEM_BYTES);

    // fork stream + events (host objects; created per call, O(1) calls total)
    cudaStream_t s1;
    cudaEvent_t eFork, eJoin;
    cudaStreamCreateWithFlags(&s1, cudaStreamNonBlocking);
    cudaEventCreateWithFlags(&eFork, cudaEventDisableTiming);
    cudaEventCreateWithFlags(&eJoin, cudaEventDisableTiming);

    // fork point on the main (captured) stream
    cudaEventRecord(eFork, 0);
    cudaStreamWaitEvent(s1, eFork, 0);

    // forked branch: down-proj weight convert (only GEMM2 needs it)
    cvt_wd<<<BW, 256, 0, s1>>>((const int4*)wd, (uint4*)pwd);
    cudaEventRecord(eJoin, s1);

    // main branch: x + gate/up converts, then GEMM1
    cvt_xw<<<BX + 2 * BW, 256>>>(
        (const float4*)x, (const int4*)wg, (const int4*)wu,
        (uint4*)px, (uint4*)pwg, (uint4*)pwu);

    {
        int mtiles = MROWS / 128;   // 64
        int ntiles = HID / 64;      // 172
        int ntotal = mtiles * ntiles;
        int grid = gpersist < ntotal ? gpersist : ntotal;
        ffn_gemm<2, 64><<<grid, 256, SMEM_BYTES>>>(
            (const __half*)px, (const __half*)pwg, (const __half*)pwu,
            pmid, sg, su, DIMN, ntiles, ntotal, HID);
    }

    // join: GEMM2 needs both g_mid (main) and pwd (forked)
    cudaStreamWaitEvent(0, eJoin, 0);

    {
        int mtiles = MROWS / 128;   // 64
        int ntiles = DIMN / 128;    // 32
        int ntotal = mtiles * ntiles;
        int grid = gpersist < ntotal ? gpersist : ntotal;
        ffn_gemm<1, 128><<<grid, 256, SMEM_BYTES>>>(
            (const __half*)pmid, (const __half*)pwd, (const __half*)pwd,
            d_out, sd, sd, HID, ntiles, ntotal, DIMN);
    }
}